// round 8
// baseline (speedup 1.0000x reference)
#include <cuda_runtime.h>
#include <cuda_fp16.h>
#include <math.h>
#include <stdint.h>

#define D  2048
#define N1 250
#define N2 27
#define SCALE 0.022097086912079608f   // 1/sqrt(2048)

// ------------------------- scratch -------------------------
__device__ __half g_xh[384 * D];                 // rows 0-255: x1 (padded), 256-287: x2, rest pad
__device__ float g_q1[N1 * D], g_k1[N1 * D], g_v1[N1 * D];
__device__ float g_q2[N2 * D], g_k2[N2 * D], g_v2[N2 * D];
__device__ float g_r1[N2];
__device__ unsigned g_cnt[N2];

// ------------------------- prep: fp32 -> fp16 activations -------------------------
__global__ void __launch_bounds__(256) prep_kernel(const float* __restrict__ x1,
                                                   const float* __restrict__ x2)
{
    int t = blockIdx.x * 256 + threadIdx.x;      // 384*256 threads, 8 elems each
    int row = t >> 8;
    int c0 = (t & 255) * 8;
    float4 f0 = make_float4(0.f, 0.f, 0.f, 0.f), f1 = f0;
    if (row < 256) {
        if (row < N1) {
            const float4* s = (const float4*)(x1 + (size_t)row * D + c0);
            f0 = s[0]; f1 = s[1];
        }
    } else {
        int r2 = row - 256;
        if (r2 < N2) {
            const float4* s = (const float4*)(x2 + (size_t)r2 * D + c0);
            f0 = s[0]; f1 = s[1];
        }
    }
    __half2 h0 = __float22half2_rn(make_float2(f0.x, f0.y));
    __half2 h1 = __float22half2_rn(make_float2(f0.z, f0.w));
    __half2 h2 = __float22half2_rn(make_float2(f1.x, f1.y));
    __half2 h3 = __float22half2_rn(make_float2(f1.z, f1.w));
    uint4 w;
    w.x = *(unsigned*)&h0; w.y = *(unsigned*)&h1;
    w.z = *(unsigned*)&h2; w.w = *(unsigned*)&h3;
    *(uint4*)(g_xh + (size_t)row * D + c0) = w;
}

__global__ void zk_kernel() {
    if (threadIdx.x < N2) { g_r1[threadIdx.x] = 0.f; g_cnt[threadIdx.x] = 0u; }
}
__global__ void znop_kernel() {}

// ------------------------- projection GEMM (fp16 mma.sync, fp32 accum) -------------------------
// 288 CTAs x 256 threads, 2 CTAs/SM. Tile 128x64, BK=32, 64 K-chunks.
// Each CTA: 2 subs of 4 warps (K-split: sub 0 even chunks, sub 1 odd), each sub
// an independent 128-thread pipeline with its own smem stages and named barrier.
#define ROWW 20                      // padded row stride in words (32 f16 + 8 pad)
#define ABUF_WORDS (128 * ROWW)      // 2560 words = 10240 B (A: 128 rows x 32 f16)
#define BBUF_WORDS (64 * ROWW)       // 1280 words =  5120 B (B:  64 rows x 32 f16)
#define SUB_WORDS (4 * ABUF_WORDS + 3 * BBUF_WORDS)   // 14080 words
#define PROJ_SMEM (2 * SUB_WORDS * 4)                 // 112640 B

__device__ __forceinline__ void mma16816(float* c, const unsigned* a, const unsigned* b) {
    asm volatile(
        "mma.sync.aligned.m16n8k16.row.col.f32.f16.f16.f32 "
        "{%0,%1,%2,%3},{%4,%5,%6,%7},{%8,%9},{%0,%1,%2,%3};"
        : "+f"(c[0]), "+f"(c[1]), "+f"(c[2]), "+f"(c[3])
        : "r"(a[0]), "r"(a[1]), "r"(a[2]), "r"(a[3]), "r"(b[0]), "r"(b[1]));
}

extern __shared__ unsigned proj_smem[];

__global__ void __launch_bounds__(256, 2) proj_kernel(
    const float* __restrict__ Wq1, const float* __restrict__ Wk1, const float* __restrict__ Wv1,
    const float* __restrict__ Wq2, const float* __restrict__ Wk2, const float* __restrict__ Wv2,
    const float* __restrict__ bq1, const float* __restrict__ bk1, const float* __restrict__ bv1,
    const float* __restrict__ bq2, const float* __restrict__ bk2, const float* __restrict__ bv2)
{
    const int tid = threadIdx.x;
    const int sub = tid >> 7;            // 0 or 1
    const int st  = tid & 127;           // thread id within sub
    const int lane = tid & 31;
    const int wid4 = (tid >> 5) & 3;     // warp id within sub

    // ---- tile decode (288 tiles of 128x64) ----
    const float* W; const float* bias; float* Cout;
    int aRow0, rowBase, Mv, nb;
    {
        int b = blockIdx.x;
        if (b < 192) {
            int p = b >> 6, r = b & 63;
            int mt = r >> 5, nt = r & 31;
            nb = nt * 64; aRow0 = mt * 128; rowBase = mt * 128; Mv = N1;
            W    = (p == 0) ? Wq1 : ((p == 1) ? Wk1 : Wv1);
            bias = (p == 0) ? bq1 : ((p == 1) ? bk1 : bv1);
            Cout = (p == 0) ? g_q1 : ((p == 1) ? g_k1 : g_v1);
        } else {
            int b2 = b - 192, p = b2 >> 5, nt = b2 & 31;
            nb = nt * 64; aRow0 = 256; rowBase = 0; Mv = N2;
            W    = (p == 0) ? Wq2 : ((p == 1) ? Wk2 : Wv2);
            bias = (p == 0) ? bq2 : ((p == 1) ? bk2 : bv2);
            Cout = (p == 0) ? g_q2 : ((p == 1) ? g_k2 : g_v2);
        }
    }

    unsigned* Asm = proj_smem + sub * SUB_WORDS;     // 4 A stages
    unsigned* Bsm = Asm + 4 * ABUF_WORDS;            // 3 B stages

    // ---- producer addressing (within 128-thread sub) ----
    const int rB = st >> 1, hB = st & 1;             // B: 2 thr/row, 16 fp32 each (64 rows)
    const float*  bp = W + (size_t)(nb + rB) * D + hB * 16;
    const __half* ap = g_xh + (size_t)(aRow0 + st) * D;   // A: 1 thr/row, 32 f16 (64B)
    unsigned* bDst = Bsm + rB * ROWW + hB * 8;
    uint32_t aDstBase;
    {
        unsigned* p0 = Asm + st * ROWW;
        asm("{ .reg .u64 t; cvta.to.shared.u64 t, %1; cvt.u32.u64 %0, t; }"
            : "=r"(aDstBase) : "l"(p0));
    }

    // ---- consumer addressing: 4 warps, 64x32 each; warpM in {0,64}, warpN in {0,32} ----
    const int warpM = (wid4 & 1) * 64;
    const int warpN = (wid4 >> 1) * 32;
    const int q = lane >> 2, c = lane & 3;
    const unsigned aIdx = (unsigned)((warpM + q) * ROWW + c);
    const unsigned bIdx = (unsigned)((warpN + q) * ROWW + c);

    float acc[4][4][4];
#pragma unroll
    for (int i = 0; i < 4; ++i)
#pragma unroll
        for (int j = 0; j < 4; ++j)
#pragma unroll
            for (int r = 0; r < 4; ++r) acc[i][j][r] = 0.f;

    float4 s0, s1, s2, s3;      // single B staging set

#define BAR_SUB() asm volatile("bar.sync %0, %1;" :: "r"(sub + 1), "r"(128) : "memory")

#define LDGB(g) do {                                                     \
        const float4* bp4 = (const float4*)(bp + (g) * 32);              \
        s0 = bp4[0]; s1 = bp4[1]; s2 = bp4[2]; s3 = bp4[3];              \
    } while (0)

#define STSB(buf) do {                                                   \
        __half2 p0 = __float22half2_rn(make_float2(s0.x, s0.y));         \
        __half2 p1 = __float22half2_rn(make_float2(s0.z, s0.w));         \
        __half2 p2 = __float22half2_rn(make_float2(s1.x, s1.y));         \
        __half2 p3 = __float22half2_rn(make_float2(s1.z, s1.w));         \
        __half2 p4 = __float22half2_rn(make_float2(s2.x, s2.y));         \
        __half2 p5 = __float22half2_rn(make_float2(s2.z, s2.w));         \
        __half2 p6 = __float22half2_rn(make_float2(s3.x, s3.y));         \
        __half2 p7 = __float22half2_rn(make_float2(s3.z, s3.w));         \
        uint4* bd = (uint4*)(bDst + (buf) * BBUF_WORDS);                 \
        bd[0] = make_uint4(*(unsigned*)&p0, *(unsigned*)&p1,             \
                           *(unsigned*)&p2, *(unsigned*)&p3);            \
        bd[1] = make_uint4(*(unsigned*)&p4, *(unsigned*)&p5,             \
                           *(unsigned*)&p6, *(unsigned*)&p7);            \
    } while (0)

// 64 contiguous bytes = 32 halves: byte offsets 0,16,32,48 == half offsets 0,8,16,24
#define CPA(ia) do {                                                     \
        uint32_t dst = aDstBase + (unsigned)(((ia) & 3) * ABUF_WORDS) * 4u; \
        const __half* src = ap + (size_t)(2 * (ia) + sub) * 32;          \
        asm volatile("cp.async.ca.shared.global [%0], [%1], 16;"         \
                     :: "r"(dst), "l"(src));                             \
        asm volatile("cp.async.ca.shared.global [%0], [%1], 16;"         \
                     :: "r"(dst + 16), "l"(src + 8));                    \
        asm volatile("cp.async.ca.shared.global [%0], [%1], 16;"         \
                     :: "r"(dst + 32), "l"(src + 16));                   \
        asm volatile("cp.async.ca.shared.global [%0], [%1], 16;"         \
                     :: "r"(dst + 48), "l"(src + 24));                   \
        asm volatile("cp.async.commit_group;" ::: "memory");             \
    } while (0)

#define COMPUTE(as, bs) do {                                             \
        const unsigned* A0 = Asm + (as) * ABUF_WORDS;                    \
        const unsigned* B0 = Bsm + (bs) * BBUF_WORDS;                    \
        _Pragma("unroll")                                                \
        for (int s = 0; s < 2; ++s) {                                    \
            unsigned af[4][4], bf[4][2];                                 \
            const unsigned so = s * 8;                                   \
            _Pragma("unroll")                                            \
            for (int i = 0; i < 4; ++i) {                                \
                unsigned base = aIdx + i * (16 * ROWW) + so;             \
                af[i][0] = A0[base];                                     \
                af[i][1] = A0[base + 8 * ROWW];                          \
                af[i][2] = A0[base + 4];                                 \
                af[i][3] = A0[base + 8 * ROWW + 4];                      \
            }                                                            \
            _Pragma("unroll")                                            \
            for (int j = 0; j < 4; ++j) {                                \
                unsigned base = bIdx + j * (8 * ROWW) + so;              \
                bf[j][0] = B0[base];                                     \
                bf[j][1] = B0[base + 4];                                 \
            }                                                            \
            _Pragma("unroll")                                            \
            for (int i = 0; i < 4; ++i)                                  \
                _Pragma("unroll")                                        \
                for (int j = 0; j < 4; ++j)                              \
                    mma16816(acc[i][j], af[i], bf[j]);                   \
        }                                                                \
    } while (0)

    // ---- prologue ----
    CPA(0); CPA(1); CPA(2);
    LDGB(sub);            // B for sub-iter 0 (global chunk = sub)
    STSB(0);
    LDGB(2 + sub);        // B for sub-iter 1

    int bcur = 0;
#pragma unroll 1
    for (int i = 0; i < 32; ++i) {
        int bnext = bcur + 1; if (bnext == 3) bnext = 0;
        if (i + 1 < 32) STSB(bnext);                 // stage B(i+1)
        if (i + 2 < 32) LDGB(2 * (i + 2) + sub);     // fetch B(i+2)
        if (i < 30)      asm volatile("cp.async.wait_group 2;" ::: "memory");
        else if (i == 30) asm volatile("cp.async.wait_group 1;" ::: "memory");
        else             asm volatile("cp.async.wait_group 0;" ::: "memory");
        BAR_SUB();
        if (i + 3 < 32) CPA(i + 3);                  // safe: post-barrier
        COMPUTE(i & 3, bcur);
        bcur = bnext;
    }

    // ---- reduction (sub1 acc -> smem, sub0 adds) + epilogue ----
    __syncthreads();
    float* red = (float*)proj_smem;                  // 128 x 68 fp32 pitch
    if (sub == 1) {
#pragma unroll
        for (int i = 0; i < 4; ++i) {
            const int r0 = warpM + i * 16 + q;
#pragma unroll
            for (int j = 0; j < 4; ++j) {
                const int col = warpN + j * 8 + 2 * c;
                *(float2*)(red + r0 * 68 + col)       = make_float2(acc[i][j][0], acc[i][j][1]);
                *(float2*)(red + (r0 + 8) * 68 + col) = make_float2(acc[i][j][2], acc[i][j][3]);
            }
        }
    }
    __syncthreads();
    if (sub == 0) {
#pragma unroll
        for (int i = 0; i < 4; ++i) {
            const int r0 = rowBase + warpM + i * 16 + q;
            const int rl = warpM + i * 16 + q;
            const bool ok0 = r0 < Mv, ok1 = (r0 + 8) < Mv;
#pragma unroll
            for (int j = 0; j < 4; ++j) {
                const int col = nb + warpN + j * 8 + 2 * c;
                const int cl = warpN + j * 8 + 2 * c;
                const float2 bv = *(const float2*)(bias + col);
                float2 e0 = *(const float2*)(red + rl * 68 + cl);
                float2 e1 = *(const float2*)(red + (rl + 8) * 68 + cl);
                if (ok0) {
                    float2 o = make_float2(acc[i][j][0] + e0.x + bv.x,
                                           acc[i][j][1] + e0.y + bv.y);
                    *(float2*)(Cout + (size_t)r0 * D + col) = o;
                }
                if (ok1) {
                    float2 o = make_float2(acc[i][j][2] + e1.x + bv.x,
                                           acc[i][j][3] + e1.y + bv.y);
                    *(float2*)(Cout + (size_t)(r0 + 8) * D + col) = o;
                }
            }
        }
    }
#undef BAR_SUB
#undef LDGB
#undef STSB
#undef CPA
#undef COMPUTE
}

// ------------------------- scores + fc + ctx2 + probs1 + fused ctx1 -------------------------
__global__ void __launch_bounds__(256) scores_kernel(
    const float* __restrict__ w_fc1, const float* __restrict__ b_fc1,
    const float* __restrict__ w_fc2, const float* __restrict__ b_fc2,
    float* __restrict__ out)
{
    __shared__ float qv_s[D];
    __shared__ float ps[32];
    __shared__ float red[8];
    __shared__ int   sflag;
    __shared__ float sr1;
    const int tid = threadIdx.x;
    const int lane = tid & 31, w = tid >> 5;

    float* out_ctx2   = out;
    float* out_probs2 = out + (size_t)N1 * D;
    float* out_ctx1   = out + (size_t)N1 * D + N1 * N2;
    float* out_probs1 = out + (size_t)N1 * D + N1 * N2 + (size_t)N2 * D;

    if (blockIdx.x < N1) {
        const int m = blockIdx.x;
        for (int k = tid; k < D; k += 256) qv_s[k] = g_q1[(size_t)m * D + k];
        __syncthreads();
        const float4* qv = (const float4*)qv_s;
        for (int n = w; n < N2; n += 8) {
            const float4* kr = (const float4*)(g_k2 + (size_t)n * D);
            float p = 0.f;
            for (int k = lane; k < D / 4; k += 32) {
                float4 a = qv[k], b = kr[k];
                p += a.x * b.x + a.y * b.y + a.z * b.z + a.w * b.w;
            }
#pragma unroll
            for (int o = 16; o; o >>= 1) p += __shfl_xor_sync(0xffffffffu, p, o);
            if (lane == 0) {
                float pr = 1.f / (1.f + expf(-p * SCALE));
                ps[n] = pr;
                out_probs2[(size_t)m * N2 + n] = pr;
            }
        }
        __syncthreads();
        float r2 = 0.f;
#pragma unroll
        for (int n = 0; n < N2; ++n) r2 += ps[n] * w_fc2[n];
        const float bf2 = b_fc2[0];
        for (int dd = tid; dd < D; dd += 256)
            out_ctx2[(size_t)m * D + dd] = g_v1[(size_t)m * D + dd] * r2 + bf2;
    } else {
        const int j = blockIdx.x - N1;
        const int t = j % N2;            // 0..26
        const int i0 = (j / N2) * 25;    // 10 chunks x 25 rows
        for (int k = tid; k < D; k += 256) qv_s[k] = g_q2[(size_t)t * D + k];
        __syncthreads();
        const float4* qv = (const float4*)qv_s;
        float acc = 0.f;
        for (int il = w; il < 25; il += 8) {
            const int i = i0 + il;
            const float4* kr = (const float4*)(g_k1 + (size_t)i * D);
            float p = 0.f;
            for (int k = lane; k < D / 4; k += 32) {
                float4 a = qv[k], b = kr[k];
                p += a.x * b.x + a.y * b.y + a.z * b.z + a.w * b.w;
            }
#pragma unroll
            for (int o = 16; o; o >>= 1) p += __shfl_xor_sync(0xffffffffu, p, o);
            if (lane == 0) {
                float pr = 1.f / (1.f + expf(-p * SCALE));
                out_probs1[(size_t)t * N1 + i] = pr;
                acc += pr * w_fc1[i];
            }
        }
        if (lane == 0) red[w] = acc;
        __syncthreads();
        if (tid == 0) {
            float s = 0.f;
#pragma unroll
            for (int ww = 0; ww < 8; ++ww) s += red[ww];
            atomicAdd(&g_r1[t], s);
            __threadfence();
            unsigned old = atomicAdd(&g_cnt[t], 1u);
            sflag = (old == 9u);                      // last of 10 chunks
            if (sflag) {
                __threadfence();
                sr1 = *((volatile float*)&g_r1[t]);
            }
        }
        __syncthreads();
        if (sflag) {
            const float r1 = sr1;
            const float bf1 = b_fc1[0];
            for (int dd = tid; dd < D; dd += 256)
                out_ctx1[(size_t)t * D + dd] = g_v2[(size_t)t * D + dd] * r1 + bf1;
        }
    }
}

// ------------------------- launch -------------------------
extern "C" void kernel_launch(void* const* d_in, const int* in_sizes, int n_in,
                              void* d_out, int out_size)
{
    const float* x1  = (const float*)d_in[0];
    const float* x2  = (const float*)d_in[1];
    const float* Wq1 = (const float*)d_in[2];
    const float* bq1 = (const float*)d_in[3];
    const float* Wk1 = (const float*)d_in[4];
    const float* bk1 = (const float*)d_in[5];
    const float* Wv1 = (const float*)d_in[6];
    const float* bv1 = (const float*)d_in[7];
    const float* Wq2 = (const float*)d_in[8];
    const float* bq2 = (const float*)d_in[9];
    const float* Wk2 = (const float*)d_in[10];
    const float* bk2 = (const float*)d_in[11];
    const float* Wv2 = (const float*)d_in[12];
    const float* bv2 = (const float*)d_in[13];
    const float* wf1 = (const float*)d_in[14];
    const float* bf1 = (const float*)d_in[15];
    const float* wf2 = (const float*)d_in[16];
    const float* bf2 = (const float*)d_in[17];
    float* out = (float*)d_out;

    static int smem_set = 0;
    if (!smem_set) {
        cudaFuncSetAttribute(proj_kernel, cudaFuncAttributeMaxDynamicSharedMemorySize, PROJ_SMEM);
        smem_set = 1;
    }

    prep_kernel<<<384, 256>>>(x1, x2);
    zk_kernel<<<1, 32>>>();
    znop_kernel<<<1, 32>>>();
    proj_kernel<<<288, 256, PROJ_SMEM>>>(Wq1, Wk1, Wv1, Wq2, Wk2, Wv2,
                                         bq1, bk1, bv1, bq2, bk2, bv2);
    scores_kernel<<<520, 256>>>(wf1, bf1, wf2, bf2, out);
}

// round 9
// speedup vs baseline: 1.4969x; 1.4969x over previous
#include <cuda_runtime.h>
#include <cuda_fp16.h>
#include <math.h>
#include <stdint.h>

#define D  2048
#define N1 250
#define N2 27
#define SCALE 0.022097086912079608f   // 1/sqrt(2048)

// ------------------------- scratch -------------------------
__device__ __half g_xh[384 * D];                 // rows 0-255: x1 (padded), 256-287: x2, rest pad
__device__ float g_q1[N1 * D], g_k1[N1 * D], g_v1[N1 * D];
__device__ float g_q2[N2 * D], g_k2[N2 * D], g_v2[N2 * D];
__device__ float g_r1[N2];
__device__ unsigned g_cnt[N2];

// ------------------------- prep: fp32 -> fp16 activations -------------------------
__global__ void __launch_bounds__(256) prep_kernel(const float* __restrict__ x1,
                                                   const float* __restrict__ x2)
{
    int t = blockIdx.x * 256 + threadIdx.x;      // 384*256 threads, 8 elems each
    int row = t >> 8;
    int c0 = (t & 255) * 8;
    float4 f0 = make_float4(0.f, 0.f, 0.f, 0.f), f1 = f0;
    if (row < 256) {
        if (row < N1) {
            const float4* s = (const float4*)(x1 + (size_t)row * D + c0);
            f0 = s[0]; f1 = s[1];
        }
    } else {
        int r2 = row - 256;
        if (r2 < N2) {
            const float4* s = (const float4*)(x2 + (size_t)r2 * D + c0);
            f0 = s[0]; f1 = s[1];
        }
    }
    __half2 h0 = __float22half2_rn(make_float2(f0.x, f0.y));
    __half2 h1 = __float22half2_rn(make_float2(f0.z, f0.w));
    __half2 h2 = __float22half2_rn(make_float2(f1.x, f1.y));
    __half2 h3 = __float22half2_rn(make_float2(f1.z, f1.w));
    uint4 w;
    w.x = *(unsigned*)&h0; w.y = *(unsigned*)&h1;
    w.z = *(unsigned*)&h2; w.w = *(unsigned*)&h3;
    *(uint4*)(g_xh + (size_t)row * D + c0) = w;
}

__global__ void zk_kernel() {
    if (threadIdx.x < N2) { g_r1[threadIdx.x] = 0.f; g_cnt[threadIdx.x] = 0u; }
}
__global__ void znop_kernel() {}

// ------------------------- projection GEMM (fp16 mma.sync, fp32 accum) -------------------------
// 144 CTAs x 512 threads (1 CTA/SM). Tile 128x128, BK=32, 64 K-chunks.
// Sub 0 (warps 0-7) even chunks, sub 1 (warps 8-15) odd chunks; independent
// 256-thread pipelines with named barriers. Fragments via ldmatrix.x4.
#define ROWW 20                      // padded row stride in words (32 f16 + 8 pad) = 80 B
#define ABUF_WORDS (128 * ROWW)      // 10240 B
#define BBUF_WORDS (128 * ROWW)
#define ABUF_BYTES (ABUF_WORDS * 4)
#define BBUF_BYTES (BBUF_WORDS * 4)
#define SUB_WORDS (4 * ABUF_WORDS + 3 * BBUF_WORDS)   // 17920 words
#define PROJ_SMEM (2 * SUB_WORDS * 4)                 // 143360 B

__device__ __forceinline__ void mma16816(float* c, const unsigned* a, const unsigned* b) {
    asm volatile(
        "mma.sync.aligned.m16n8k16.row.col.f32.f16.f16.f32 "
        "{%0,%1,%2,%3},{%4,%5,%6,%7},{%8,%9},{%0,%1,%2,%3};"
        : "+f"(c[0]), "+f"(c[1]), "+f"(c[2]), "+f"(c[3])
        : "r"(a[0]), "r"(a[1]), "r"(a[2]), "r"(a[3]), "r"(b[0]), "r"(b[1]));
}
#define LDSM4(r0, r1, r2, r3, addr)                                      \
    asm volatile("ldmatrix.sync.aligned.m8n8.x4.shared.b16 {%0,%1,%2,%3}, [%4];" \
                 : "=r"(r0), "=r"(r1), "=r"(r2), "=r"(r3) : "r"(addr))

extern __shared__ unsigned proj_smem[];

__global__ void __launch_bounds__(512, 1) proj_kernel(
    const float* __restrict__ Wq1, const float* __restrict__ Wk1, const float* __restrict__ Wv1,
    const float* __restrict__ Wq2, const float* __restrict__ Wk2, const float* __restrict__ Wv2,
    const float* __restrict__ bq1, const float* __restrict__ bk1, const float* __restrict__ bv1,
    const float* __restrict__ bq2, const float* __restrict__ bk2, const float* __restrict__ bv2)
{
    const int tid = threadIdx.x;
    const int sub = tid >> 8;            // 0 or 1
    const int st  = tid & 255;           // thread id within sub
    const int lane = tid & 31;
    const int wid8 = (tid >> 5) & 7;     // warp id within sub

    // ---- tile decode ----
    const float* W; const float* bias; float* Cout;
    int aRow0, rowBase, Mv, nb;
    {
        int b = blockIdx.x;
        if (b < 96) {
            int p = b >> 5, mt = (b >> 4) & 1, nt = b & 15;
            nb = nt * 128; aRow0 = mt * 128; rowBase = mt * 128; Mv = N1;
            W    = (p == 0) ? Wq1 : ((p == 1) ? Wk1 : Wv1);
            bias = (p == 0) ? bq1 : ((p == 1) ? bk1 : bv1);
            Cout = (p == 0) ? g_q1 : ((p == 1) ? g_k1 : g_v1);
        } else {
            int b2 = b - 96, p = b2 >> 4, nt = b2 & 15;
            nb = nt * 128; aRow0 = 256; rowBase = 0; Mv = N2;
            W    = (p == 0) ? Wq2 : ((p == 1) ? Wk2 : Wv2);
            bias = (p == 0) ? bq2 : ((p == 1) ? bk2 : bv2);
            Cout = (p == 0) ? g_q2 : ((p == 1) ? g_k2 : g_v2);
        }
    }

    unsigned* Asm = proj_smem + sub * SUB_WORDS;     // 4 A stages
    unsigned* Bsm = Asm + 4 * ABUF_WORDS;            // 3 B stages
    uint32_t AsmU32, BsmU32;
    asm("{ .reg .u64 t; cvta.to.shared.u64 t, %1; cvt.u32.u64 %0, t; }" : "=r"(AsmU32) : "l"(Asm));
    asm("{ .reg .u64 t; cvta.to.shared.u64 t, %1; cvt.u32.u64 %0, t; }" : "=r"(BsmU32) : "l"(Bsm));

    // ---- producer addressing (within sub) ----
    const int rB = st >> 1, hB = st & 1;             // B: 2 thr/row, 16 fp32
    const int rA = st & 127, hA = (st >> 7) & 1;     // A: 2 thr/row, 16 fp16
    const float*  bp = W + (size_t)(nb + rB) * D + hB * 16;
    const __half* ap = g_xh + (size_t)(aRow0 + rA) * D + hA * 16;
    unsigned* bDst = Bsm + rB * ROWW + hB * 8;
    uint32_t aDstBase;
    {
        unsigned* p0 = Asm + rA * ROWW + hA * 8;
        asm("{ .reg .u64 t; cvta.to.shared.u64 t, %1; cvt.u32.u64 %0, t; }"
            : "=r"(aDstBase) : "l"(p0));
    }

    // ---- consumer addressing (ldmatrix lane offsets, byte units) ----
    const int warpM = (wid8 & 1) * 64;
    const int warpN = (wid8 >> 1) * 32;
    const int q = lane >> 2, c = lane & 3;
    // A x4 tile groups: g0 rows+0-7 k0 | g1 rows+8-15 k0 | g2 rows+0-7 k+16B | g3 rows+8-15 k+16B
    const uint32_t aoff = (uint32_t)(((lane & 7) + ((lane >> 3) & 1) * 8) * 80 + (lane >> 4) * 16);
    // B x4 tile groups: j = lane>>3, row n = warpN + lane
    const uint32_t boff = (uint32_t)(lane * 80);
    const uint32_t aBase0 = AsmU32 + (uint32_t)(warpM * 80) + aoff;
    const uint32_t bBase0 = BsmU32 + (uint32_t)(warpN * 80) + boff;

    float acc[4][4][4];
#pragma unroll
    for (int i = 0; i < 4; ++i)
#pragma unroll
        for (int j = 0; j < 4; ++j)
#pragma unroll
            for (int r = 0; r < 4; ++r) acc[i][j][r] = 0.f;

    float4 s0, s1, s2, s3;      // single B staging set

#define BAR_SUB() asm volatile("bar.sync %0, %1;" :: "r"(sub + 1), "r"(256) : "memory")

#define LDGB(g) do {                                                     \
        const float4* bp4 = (const float4*)(bp + (g) * 32);              \
        s0 = bp4[0]; s1 = bp4[1]; s2 = bp4[2]; s3 = bp4[3];              \
    } while (0)

#define STSB(buf) do {                                                   \
        __half2 p0 = __float22half2_rn(make_float2(s0.x, s0.y));         \
        __half2 p1 = __float22half2_rn(make_float2(s0.z, s0.w));         \
        __half2 p2 = __float22half2_rn(make_float2(s1.x, s1.y));         \
        __half2 p3 = __float22half2_rn(make_float2(s1.z, s1.w));         \
        __half2 p4 = __float22half2_rn(make_float2(s2.x, s2.y));         \
        __half2 p5 = __float22half2_rn(make_float2(s2.z, s2.w));         \
        __half2 p6 = __float22half2_rn(make_float2(s3.x, s3.y));         \
        __half2 p7 = __float22half2_rn(make_float2(s3.z, s3.w));         \
        uint4* bd = (uint4*)(bDst + (buf) * BBUF_WORDS);                 \
        bd[0] = make_uint4(*(unsigned*)&p0, *(unsigned*)&p1,             \
                           *(unsigned*)&p2, *(unsigned*)&p3);            \
        bd[1] = make_uint4(*(unsigned*)&p4, *(unsigned*)&p5,             \
                           *(unsigned*)&p6, *(unsigned*)&p7);            \
    } while (0)

#define CPA(ia) do {                                                     \
        uint32_t dst = aDstBase + (unsigned)(((ia) & 3) * ABUF_WORDS) * 4u; \
        const __half* src = ap + (size_t)(2 * (ia) + sub) * 32;          \
        asm volatile("cp.async.ca.shared.global [%0], [%1], 16;"         \
                     :: "r"(dst), "l"(src));                             \
        asm volatile("cp.async.ca.shared.global [%0], [%1], 16;"         \
                     :: "r"(dst + 16), "l"(src + 8));                    \
        asm volatile("cp.async.commit_group;" ::: "memory");             \
    } while (0)

#define COMPUTE(as, bs) do {                                             \
        const uint32_t Aa = aBase0 + (uint32_t)((as) * ABUF_BYTES);      \
        const uint32_t Ba = bBase0 + (uint32_t)((bs) * BBUF_BYTES);      \
        _Pragma("unroll")                                                \
        for (int s = 0; s < 2; ++s) {                                    \
            unsigned bf[4][2];                                           \
            LDSM4(bf[0][0], bf[1][0], bf[2][0], bf[3][0], Ba + s * 32);  \
            LDSM4(bf[0][1], bf[1][1], bf[2][1], bf[3][1], Ba + s * 32 + 16); \
            _Pragma("unroll")                                            \
            for (int i = 0; i < 4; ++i) {                                \
                unsigned af[4];                                          \
                LDSM4(af[0], af[1], af[2], af[3], Aa + i * (16 * 80) + s * 32); \
                _Pragma("unroll")                                        \
                for (int j = 0; j < 4; ++j)                              \
                    mma16816(acc[i][j], af, bf[j]);                      \
            }                                                            \
        }                                                                \
    } while (0)

    // ---- prologue ----
    CPA(0); CPA(1); CPA(2);
    LDGB(sub);            // B for sub-iter 0 (global chunk = sub)
    STSB(0);
    LDGB(2 + sub);        // B for sub-iter 1

    int bcur = 0;
#pragma unroll 1
    for (int i = 0; i < 32; ++i) {
        int bnext = bcur + 1; if (bnext == 3) bnext = 0;
        if (i + 1 < 32) STSB(bnext);                 // stage B(i+1)
        if (i + 2 < 32) LDGB(2 * (i + 2) + sub);     // fetch B(i+2)
        if (i < 30)      asm volatile("cp.async.wait_group 2;" ::: "memory");
        else if (i == 30) asm volatile("cp.async.wait_group 1;" ::: "memory");
        else             asm volatile("cp.async.wait_group 0;" ::: "memory");
        BAR_SUB();
        if (i + 3 < 32) CPA(i + 3);                  // safe: post-barrier
        COMPUTE(i & 3, bcur);
        bcur = bnext;
    }

    // ---- reduction (sub1 acc -> smem, sub0 adds) + epilogue ----
    __syncthreads();
    float* red = (float*)proj_smem;                  // 128 x 132 fp32 pitch
    if (sub == 1) {
#pragma unroll
        for (int i = 0; i < 4; ++i) {
            const int r0 = warpM + i * 16 + q;
#pragma unroll
            for (int j = 0; j < 4; ++j) {
                const int col = warpN + j * 8 + 2 * c;
                *(float2*)(red + r0 * 132 + col)       = make_float2(acc[i][j][0], acc[i][j][1]);
                *(float2*)(red + (r0 + 8) * 132 + col) = make_float2(acc[i][j][2], acc[i][j][3]);
            }
        }
    }
    __syncthreads();
    if (sub == 0) {
#pragma unroll
        for (int i = 0; i < 4; ++i) {
            const int r0 = rowBase + warpM + i * 16 + q;
            const int rl = warpM + i * 16 + q;
            const bool ok0 = r0 < Mv, ok1 = (r0 + 8) < Mv;
#pragma unroll
            for (int j = 0; j < 4; ++j) {
                const int col = nb + warpN + j * 8 + 2 * c;
                const int cl = warpN + j * 8 + 2 * c;
                const float2 bv = *(const float2*)(bias + col);
                float2 e0 = *(const float2*)(red + rl * 132 + cl);
                float2 e1 = *(const float2*)(red + (rl + 8) * 132 + cl);
                if (ok0) {
                    float2 o = make_float2(acc[i][j][0] + e0.x + bv.x,
                                           acc[i][j][1] + e0.y + bv.y);
                    *(float2*)(Cout + (size_t)r0 * D + col) = o;
                }
                if (ok1) {
                    float2 o = make_float2(acc[i][j][2] + e1.x + bv.x,
                                           acc[i][j][3] + e1.y + bv.y);
                    *(float2*)(Cout + (size_t)(r0 + 8) * D + col) = o;
                }
            }
        }
    }
#undef BAR_SUB
#undef LDGB
#undef STSB
#undef CPA
#undef COMPUTE
}

// ------------------------- scores + fc + ctx2 + probs1 + fused ctx1 -------------------------
__global__ void __launch_bounds__(256) scores_kernel(
    const float* __restrict__ w_fc1, const float* __restrict__ b_fc1,
    const float* __restrict__ w_fc2, const float* __restrict__ b_fc2,
    float* __restrict__ out)
{
    __shared__ float qv_s[D];
    __shared__ float ps[32];
    __shared__ float red[8];
    __shared__ int   sflag;
    __shared__ float sr1;
    const int tid = threadIdx.x;
    const int lane = tid & 31, w = tid >> 5;

    float* out_ctx2   = out;
    float* out_probs2 = out + (size_t)N1 * D;
    float* out_ctx1   = out + (size_t)N1 * D + N1 * N2;
    float* out_probs1 = out + (size_t)N1 * D + N1 * N2 + (size_t)N2 * D;

    if (blockIdx.x < N1) {
        const int m = blockIdx.x;
        for (int k = tid; k < D; k += 256) qv_s[k] = g_q1[(size_t)m * D + k];
        __syncthreads();
        const float4* qv = (const float4*)qv_s;
        for (int n = w; n < N2; n += 8) {
            const float4* kr = (const float4*)(g_k2 + (size_t)n * D);
            float p = 0.f;
            for (int k = lane; k < D / 4; k += 32) {
                float4 a = qv[k], b = kr[k];
                p += a.x * b.x + a.y * b.y + a.z * b.z + a.w * b.w;
            }
#pragma unroll
            for (int o = 16; o; o >>= 1) p += __shfl_xor_sync(0xffffffffu, p, o);
            if (lane == 0) {
                float pr = 1.f / (1.f + expf(-p * SCALE));
                ps[n] = pr;
                out_probs2[(size_t)m * N2 + n] = pr;
            }
        }
        __syncthreads();
        float r2 = 0.f;
#pragma unroll
        for (int n = 0; n < N2; ++n) r2 += ps[n] * w_fc2[n];
        const float bf2 = b_fc2[0];
        for (int dd = tid; dd < D; dd += 256)
            out_ctx2[(size_t)m * D + dd] = g_v1[(size_t)m * D + dd] * r2 + bf2;
    } else {
        const int j = blockIdx.x - N1;
        const int t = j % N2;            // 0..26
        const int i0 = (j / N2) * 25;    // 10 chunks x 25 rows
        for (int k = tid; k < D; k += 256) qv_s[k] = g_q2[(size_t)t * D + k];
        __syncthreads();
        const float4* qv = (const float4*)qv_s;
        float acc = 0.f;
        for (int il = w; il < 25; il += 8) {
            const int i = i0 + il;
            const float4* kr = (const float4*)(g_k1 + (size_t)i * D);
            float p = 0.f;
            for (int k = lane; k < D / 4; k += 32) {
                float4 a = qv[k], b = kr[k];
                p += a.x * b.x + a.y * b.y + a.z * b.z + a.w * b.w;
            }
#pragma unroll
            for (int o = 16; o; o >>= 1) p += __shfl_xor_sync(0xffffffffu, p, o);
            if (lane == 0) {
                float pr = 1.f / (1.f + expf(-p * SCALE));
                out_probs1[(size_t)t * N1 + i] = pr;
                acc += pr * w_fc1[i];
            }
        }
        if (lane == 0) red[w] = acc;
        __syncthreads();
        if (tid == 0) {
            float s = 0.f;
#pragma unroll
            for (int ww = 0; ww < 8; ++ww) s += red[ww];
            atomicAdd(&g_r1[t], s);
            __threadfence();
            unsigned old = atomicAdd(&g_cnt[t], 1u);
            sflag = (old == 9u);                      // last of 10 chunks
            if (sflag) {
                __threadfence();
                sr1 = *((volatile float*)&g_r1[t]);
            }
        }
        __syncthreads();
        if (sflag) {
            const float r1 = sr1;
            const float bf1 = b_fc1[0];
            for (int dd = tid; dd < D; dd += 256)
                out_ctx1[(size_t)t * D + dd] = g_v2[(size_t)t * D + dd] * r1 + bf1;
        }
    }
}

// ------------------------- launch -------------------------
extern "C" void kernel_launch(void* const* d_in, const int* in_sizes, int n_in,
                              void* d_out, int out_size)
{
    const float* x1  = (const float*)d_in[0];
    const float* x2  = (const float*)d_in[1];
    const float* Wq1 = (const float*)d_in[2];
    const float* bq1 = (const float*)d_in[3];
    const float* Wk1 = (const float*)d_in[4];
    const float* bk1 = (const float*)d_in[5];
    const float* Wv1 = (const float*)d_in[6];
    const float* bv1 = (const float*)d_in[7];
    const float* Wq2 = (const float*)d_in[8];
    const float* bq2 = (const float*)d_in[9];
    const float* Wk2 = (const float*)d_in[10];
    const float* bk2 = (const float*)d_in[11];
    const float* Wv2 = (const float*)d_in[12];
    const float* bv2 = (const float*)d_in[13];
    const float* wf1 = (const float*)d_in[14];
    const float* bf1 = (const float*)d_in[15];
    const float* wf2 = (const float*)d_in[16];
    const float* bf2 = (const float*)d_in[17];
    float* out = (float*)d_out;

    static int smem_set = 0;
    if (!smem_set) {
        cudaFuncSetAttribute(proj_kernel, cudaFuncAttributeMaxDynamicSharedMemorySize, PROJ_SMEM);
        smem_set = 1;
    }

    prep_kernel<<<384, 256>>>(x1, x2);
    zk_kernel<<<1, 32>>>();
    znop_kernel<<<1, 32>>>();
    proj_kernel<<<144, 512, PROJ_SMEM>>>(Wq1, Wk1, Wv1, Wq2, Wk2, Wv2,
                                         bq1, bk1, bv1, bq2, bk2, bv2);
    scores_kernel<<<520, 256>>>(wf1, bf1, wf2, bf2, out);
}

// round 10
// speedup vs baseline: 1.5758x; 1.0527x over previous
#include <cuda_runtime.h>
#include <cuda_fp16.h>
#include <math.h>
#include <stdint.h>

#define D  2048
#define N1 250
#define N2 27
#define SCALE 0.022097086912079608f   // 1/sqrt(2048)

// ------------------------- scratch -------------------------
__device__ __half g_xh[384 * D];                 // rows 0-255: x1 (padded), 256-287: x2, rest pad
__device__ float g_q1[N1 * D], g_k1[N1 * D], g_v1[N1 * D];
__device__ float g_q2[N2 * D], g_k2[N2 * D], g_v2[N2 * D];
__device__ __half g_q1h[256 * D], g_k1h[256 * D];   // fp16 copies (pad rows stay 0)
__device__ __half g_q2h[32 * D],  g_k2h[32 * D];
__device__ float gS[2][256 * 32];                // [0]=S2 (q1.k2T), [1]=S1T (k1.q2T)

// ------------------------- prep: fp32 -> fp16 activations -------------------------
__global__ void __launch_bounds__(256) prep_kernel(const float* __restrict__ x1,
                                                   const float* __restrict__ x2)
{
    int t = blockIdx.x * 256 + threadIdx.x;      // 384*256 threads, 8 elems each
    int row = t >> 8;
    int c0 = (t & 255) * 8;
    float4 f0 = make_float4(0.f, 0.f, 0.f, 0.f), f1 = f0;
    if (row < 256) {
        if (row < N1) {
            const float4* s = (const float4*)(x1 + (size_t)row * D + c0);
            f0 = s[0]; f1 = s[1];
        }
    } else {
        int r2 = row - 256;
        if (r2 < N2) {
            const float4* s = (const float4*)(x2 + (size_t)r2 * D + c0);
            f0 = s[0]; f1 = s[1];
        }
    }
    __half2 h0 = __float22half2_rn(make_float2(f0.x, f0.y));
    __half2 h1 = __float22half2_rn(make_float2(f0.z, f0.w));
    __half2 h2 = __float22half2_rn(make_float2(f1.x, f1.y));
    __half2 h3 = __float22half2_rn(make_float2(f1.z, f1.w));
    uint4 w;
    w.x = *(unsigned*)&h0; w.y = *(unsigned*)&h1;
    w.z = *(unsigned*)&h2; w.w = *(unsigned*)&h3;
    *(uint4*)(g_xh + (size_t)row * D + c0) = w;
}

// zero the score accumulators (every launch — graph replays)
__global__ void __launch_bounds__(256) zk_kernel() {
    int i = blockIdx.x * 256 + threadIdx.x;      // 64*256 = 16384 = 2*256*32
    ((float*)gS)[i] = 0.f;
}

// ------------------------- projection GEMM (fp16 mma.sync, fp32 accum) -------------------------
// 144 CTAs x 512 threads (1 CTA/SM). Tile 128x128, BK=32, 64 K-chunks.
// Sub 0 (warps 0-7) even chunks, sub 1 (warps 8-15) odd chunks; independent
// 256-thread pipelines with named barriers. Fragments via ldmatrix.x4.
#define ROWW 20                      // padded row stride in words (32 f16 + 8 pad) = 80 B
#define ABUF_WORDS (128 * ROWW)      // 10240 B
#define BBUF_WORDS (128 * ROWW)
#define ABUF_BYTES (ABUF_WORDS * 4)
#define BBUF_BYTES (BBUF_WORDS * 4)
#define SUB_WORDS (4 * ABUF_WORDS + 3 * BBUF_WORDS)   // 17920 words
#define PROJ_SMEM (2 * SUB_WORDS * 4)                 // 143360 B

__device__ __forceinline__ void mma16816(float* c, const unsigned* a, const unsigned* b) {
    asm volatile(
        "mma.sync.aligned.m16n8k16.row.col.f32.f16.f16.f32 "
        "{%0,%1,%2,%3},{%4,%5,%6,%7},{%8,%9},{%0,%1,%2,%3};"
        : "+f"(c[0]), "+f"(c[1]), "+f"(c[2]), "+f"(c[3])
        : "r"(a[0]), "r"(a[1]), "r"(a[2]), "r"(a[3]), "r"(b[0]), "r"(b[1]));
}
#define LDSM4(r0, r1, r2, r3, addr)                                      \
    asm volatile("ldmatrix.sync.aligned.m8n8.x4.shared.b16 {%0,%1,%2,%3}, [%4];" \
                 : "=r"(r0), "=r"(r1), "=r"(r2), "=r"(r3) : "r"(addr))

extern __shared__ unsigned proj_smem[];

__global__ void __launch_bounds__(512, 1) proj_kernel(
    const float* __restrict__ Wq1, const float* __restrict__ Wk1, const float* __restrict__ Wv1,
    const float* __restrict__ Wq2, const float* __restrict__ Wk2, const float* __restrict__ Wv2,
    const float* __restrict__ bq1, const float* __restrict__ bk1, const float* __restrict__ bv1,
    const float* __restrict__ bq2, const float* __restrict__ bk2, const float* __restrict__ bv2)
{
    const int tid = threadIdx.x;
    const int sub = tid >> 8;            // 0 or 1
    const int st  = tid & 255;           // thread id within sub
    const int lane = tid & 31;
    const int wid8 = (tid >> 5) & 7;     // warp id within sub

    // ---- tile decode ----
    const float* W; const float* bias; float* Cout; __half* Couth;
    int aRow0, rowBase, Mv, nb;
    {
        int b = blockIdx.x;
        if (b < 96) {
            int p = b >> 5, mt = (b >> 4) & 1, nt = b & 15;
            nb = nt * 128; aRow0 = mt * 128; rowBase = mt * 128; Mv = N1;
            W    = (p == 0) ? Wq1 : ((p == 1) ? Wk1 : Wv1);
            bias = (p == 0) ? bq1 : ((p == 1) ? bk1 : bv1);
            Cout = (p == 0) ? g_q1 : ((p == 1) ? g_k1 : g_v1);
            Couth = (p == 0) ? g_q1h : ((p == 1) ? g_k1h : (__half*)0);
        } else {
            int b2 = b - 96, p = b2 >> 4, nt = b2 & 15;
            nb = nt * 128; aRow0 = 256; rowBase = 0; Mv = N2;
            W    = (p == 0) ? Wq2 : ((p == 1) ? Wk2 : Wv2);
            bias = (p == 0) ? bq2 : ((p == 1) ? bk2 : bv2);
            Cout = (p == 0) ? g_q2 : ((p == 1) ? g_k2 : g_v2);
            Couth = (p == 0) ? g_q2h : ((p == 1) ? g_k2h : (__half*)0);
        }
    }

    unsigned* Asm = proj_smem + sub * SUB_WORDS;     // 4 A stages
    unsigned* Bsm = Asm + 4 * ABUF_WORDS;            // 3 B stages
    uint32_t AsmU32, BsmU32;
    asm("{ .reg .u64 t; cvta.to.shared.u64 t, %1; cvt.u32.u64 %0, t; }" : "=r"(AsmU32) : "l"(Asm));
    asm("{ .reg .u64 t; cvta.to.shared.u64 t, %1; cvt.u32.u64 %0, t; }" : "=r"(BsmU32) : "l"(Bsm));

    // ---- producer addressing (within sub) ----
    const int rB = st >> 1, hB = st & 1;             // B: 2 thr/row, 16 fp32
    const int rA = st & 127, hA = (st >> 7) & 1;     // A: 2 thr/row, 16 fp16
    const float*  bp = W + (size_t)(nb + rB) * D + hB * 16;
    const __half* ap = g_xh + (size_t)(aRow0 + rA) * D + hA * 16;
    unsigned* bDst = Bsm + rB * ROWW + hB * 8;
    uint32_t aDstBase;
    {
        unsigned* p0 = Asm + rA * ROWW + hA * 8;
        asm("{ .reg .u64 t; cvta.to.shared.u64 t, %1; cvt.u32.u64 %0, t; }"
            : "=r"(aDstBase) : "l"(p0));
    }

    // ---- consumer addressing (ldmatrix lane offsets, byte units) ----
    const int warpM = (wid8 & 1) * 64;
    const int warpN = (wid8 >> 1) * 32;
    const int q = lane >> 2, c = lane & 3;
    const uint32_t aoff = (uint32_t)(((lane & 7) + ((lane >> 3) & 1) * 8) * 80 + (lane >> 4) * 16);
    const uint32_t boff = (uint32_t)(lane * 80);
    const uint32_t aBase0 = AsmU32 + (uint32_t)(warpM * 80) + aoff;
    const uint32_t bBase0 = BsmU32 + (uint32_t)(warpN * 80) + boff;

    float acc[4][4][4];
#pragma unroll
    for (int i = 0; i < 4; ++i)
#pragma unroll
        for (int j = 0; j < 4; ++j)
#pragma unroll
            for (int r = 0; r < 4; ++r) acc[i][j][r] = 0.f;

    float4 s0, s1, s2, s3;      // single B staging set

#define BAR_SUB() asm volatile("bar.sync %0, %1;" :: "r"(sub + 1), "r"(256) : "memory")

#define LDGB(g) do {                                                     \
        const float4* bp4 = (const float4*)(bp + (g) * 32);              \
        s0 = bp4[0]; s1 = bp4[1]; s2 = bp4[2]; s3 = bp4[3];              \
    } while (0)

#define STSB(buf) do {                                                   \
        __half2 p0 = __float22half2_rn(make_float2(s0.x, s0.y));         \
        __half2 p1 = __float22half2_rn(make_float2(s0.z, s0.w));         \
        __half2 p2 = __float22half2_rn(make_float2(s1.x, s1.y));         \
        __half2 p3 = __float22half2_rn(make_float2(s1.z, s1.w));         \
        __half2 p4 = __float22half2_rn(make_float2(s2.x, s2.y));         \
        __half2 p5 = __float22half2_rn(make_float2(s2.z, s2.w));         \
        __half2 p6 = __float22half2_rn(make_float2(s3.x, s3.y));         \
        __half2 p7 = __float22half2_rn(make_float2(s3.z, s3.w));         \
        uint4* bd = (uint4*)(bDst + (buf) * BBUF_WORDS);                 \
        bd[0] = make_uint4(*(unsigned*)&p0, *(unsigned*)&p1,             \
                           *(unsigned*)&p2, *(unsigned*)&p3);            \
        bd[1] = make_uint4(*(unsigned*)&p4, *(unsigned*)&p5,             \
                           *(unsigned*)&p6, *(unsigned*)&p7);            \
    } while (0)

#define CPA(ia) do {                                                     \
        uint32_t dst = aDstBase + (unsigned)(((ia) & 3) * ABUF_WORDS) * 4u; \
        const __half* src = ap + (size_t)(2 * (ia) + sub) * 32;          \
        asm volatile("cp.async.ca.shared.global [%0], [%1], 16;"         \
                     :: "r"(dst), "l"(src));                             \
        asm volatile("cp.async.ca.shared.global [%0], [%1], 16;"         \
                     :: "r"(dst + 16), "l"(src + 8));                    \
        asm volatile("cp.async.commit_group;" ::: "memory");             \
    } while (0)

#define COMPUTE(as, bs) do {                                             \
        const uint32_t Aa = aBase0 + (uint32_t)((as) * ABUF_BYTES);      \
        const uint32_t Ba = bBase0 + (uint32_t)((bs) * BBUF_BYTES);      \
        _Pragma("unroll")                                                \
        for (int s = 0; s < 2; ++s) {                                    \
            unsigned bf[4][2];                                           \
            LDSM4(bf[0][0], bf[1][0], bf[2][0], bf[3][0], Ba + s * 32);  \
            LDSM4(bf[0][1], bf[1][1], bf[2][1], bf[3][1], Ba + s * 32 + 16); \
            _Pragma("unroll")                                            \
            for (int i = 0; i < 4; ++i) {                                \
                unsigned af[4];                                          \
                LDSM4(af[0], af[1], af[2], af[3], Aa + i * (16 * 80) + s * 32); \
                _Pragma("unroll")                                        \
                for (int j = 0; j < 4; ++j)                              \
                    mma16816(acc[i][j], af, bf[j]);                      \
            }                                                            \
        }                                                                \
    } while (0)

    // ---- prologue ----
    CPA(0); CPA(1); CPA(2);
    LDGB(sub);            // B for sub-iter 0 (global chunk = sub)
    STSB(0);
    LDGB(2 + sub);        // B for sub-iter 1

    int bcur = 0;
#pragma unroll 1
    for (int i = 0; i < 32; ++i) {
        int bnext = bcur + 1; if (bnext == 3) bnext = 0;
        if (i + 1 < 32) STSB(bnext);                 // stage B(i+1)
        if (i + 2 < 32) LDGB(2 * (i + 2) + sub);     // fetch B(i+2)
        if (i < 30)      asm volatile("cp.async.wait_group 2;" ::: "memory");
        else if (i == 30) asm volatile("cp.async.wait_group 1;" ::: "memory");
        else             asm volatile("cp.async.wait_group 0;" ::: "memory");
        BAR_SUB();
        if (i + 3 < 32) CPA(i + 3);                  // safe: post-barrier
        COMPUTE(i & 3, bcur);
        bcur = bnext;
    }

    // ---- reduction (sub1 acc -> smem, sub0 adds) + epilogue ----
    __syncthreads();
    float* red = (float*)proj_smem;                  // 128 x 132 fp32 pitch
    if (sub == 1) {
#pragma unroll
        for (int i = 0; i < 4; ++i) {
            const int r0 = warpM + i * 16 + q;
#pragma unroll
            for (int j = 0; j < 4; ++j) {
                const int col = warpN + j * 8 + 2 * c;
                *(float2*)(red + r0 * 132 + col)       = make_float2(acc[i][j][0], acc[i][j][1]);
                *(float2*)(red + (r0 + 8) * 132 + col) = make_float2(acc[i][j][2], acc[i][j][3]);
            }
        }
    }
    __syncthreads();
    if (sub == 0) {
#pragma unroll
        for (int i = 0; i < 4; ++i) {
            const int r0 = rowBase + warpM + i * 16 + q;
            const int rl = warpM + i * 16 + q;
            const bool ok0 = r0 < Mv, ok1 = (r0 + 8) < Mv;
#pragma unroll
            for (int j = 0; j < 4; ++j) {
                const int col = nb + warpN + j * 8 + 2 * c;
                const int cl = warpN + j * 8 + 2 * c;
                const float2 bv = *(const float2*)(bias + col);
                float2 e0 = *(const float2*)(red + rl * 132 + cl);
                float2 e1 = *(const float2*)(red + (rl + 8) * 132 + cl);
                if (ok0) {
                    float2 o = make_float2(acc[i][j][0] + e0.x + bv.x,
                                           acc[i][j][1] + e0.y + bv.y);
                    *(float2*)(Cout + (size_t)r0 * D + col) = o;
                    if (Couth) {
                        __half2 h = __float22half2_rn(o);
                        *(unsigned*)(Couth + (size_t)r0 * D + col) = *(unsigned*)&h;
                    }
                }
                if (ok1) {
                    float2 o = make_float2(acc[i][j][2] + e1.x + bv.x,
                                           acc[i][j][3] + e1.y + bv.y);
                    *(float2*)(Cout + (size_t)(r0 + 8) * D + col) = o;
                    if (Couth) {
                        __half2 h = __float22half2_rn(o);
                        *(unsigned*)(Couth + (size_t)(r0 + 8) * D + col) = *(unsigned*)&h;
                    }
                }
            }
        }
    }
#undef BAR_SUB
#undef LDGB
#undef STSB
#undef CPA
#undef COMPUTE
}

// ------------------------- score GEMMs on tensor pipe -------------------------
// 32 CTAs x 256 thr: b>>4 selects GEMM (0: S2 = q1h.k2hT, 1: S1T = k1h.q2hT),
// mt = (b>>3)&1 M-tile of 128, ks = b&7 K-split of 256. fp32 atomicAdd to gS.
__global__ void __launch_bounds__(256) smma_kernel()
{
    __shared__ unsigned As[2][128 * ROWW];
    __shared__ unsigned Bs[2][32 * ROWW];
    const int tid = threadIdx.x, lane = tid & 31, w = tid >> 5;
    const int b = blockIdx.x;
    const int gemm = b >> 4, mt = (b >> 3) & 1, ks = b & 7;
    const __half* Ah = gemm ? g_k1h : g_q1h;
    const __half* Bh = gemm ? g_q2h : g_k2h;
    float* S = gS[gemm];

    const int rA = tid & 127, hA = tid >> 7;
    const __half* apA = Ah + (size_t)(mt * 128 + rA) * D + ks * 256 + hA * 16;
    const int rB = tid >> 2, qb = tid & 3;           // tid<128 only
    const __half* apB = Bh + (size_t)rB * D + ks * 256 + qb * 8;

    uint32_t aDst, bDst, AsU, BsU;
    { unsigned* p = &As[0][rA * ROWW + hA * 8];
      asm("{ .reg .u64 t; cvta.to.shared.u64 t, %1; cvt.u32.u64 %0, t; }" : "=r"(aDst) : "l"(p)); }
    { unsigned* p = &Bs[0][rB * ROWW + qb * 4];
      asm("{ .reg .u64 t; cvta.to.shared.u64 t, %1; cvt.u32.u64 %0, t; }" : "=r"(bDst) : "l"(p)); }
    asm("{ .reg .u64 t; cvta.to.shared.u64 t, %1; cvt.u32.u64 %0, t; }" : "=r"(AsU) : "l"(&As[0][0]));
    asm("{ .reg .u64 t; cvta.to.shared.u64 t, %1; cvt.u32.u64 %0, t; }" : "=r"(BsU) : "l"(&Bs[0][0]));

    const uint32_t aoff = (uint32_t)(((lane & 7) + ((lane >> 3) & 1) * 8) * 80 + (lane >> 4) * 16);
    const uint32_t aBase = AsU + (uint32_t)(w * 16 * 80) + aoff;
    const uint32_t bBase = BsU + (uint32_t)(lane * 80);

    float acc[4][4];
#pragma unroll
    for (int j = 0; j < 4; ++j)
#pragma unroll
        for (int r = 0; r < 4; ++r) acc[j][r] = 0.f;

#define SCPA(cc, buf) do {                                               \
        uint32_t da = aDst + (buf) * (128 * ROWW * 4);                   \
        const __half* sa = apA + (cc) * 32;                              \
        asm volatile("cp.async.ca.shared.global [%0], [%1], 16;" :: "r"(da), "l"(sa)); \
        asm volatile("cp.async.ca.shared.global [%0], [%1], 16;" :: "r"(da + 16), "l"(sa + 8)); \
        if (tid < 128) {                                                 \
            uint32_t db = bDst + (buf) * (32 * ROWW * 4);                \
            const __half* sb = apB + (cc) * 32;                          \
            asm volatile("cp.async.ca.shared.global [%0], [%1], 16;" :: "r"(db), "l"(sb)); \
        }                                                                \
        asm volatile("cp.async.commit_group;" ::: "memory");             \
    } while (0)

    SCPA(0, 0); SCPA(1, 1);
#pragma unroll 1
    for (int cc = 0; cc < 8; ++cc) {
        if (cc < 7) asm volatile("cp.async.wait_group 1;" ::: "memory");
        else        asm volatile("cp.async.wait_group 0;" ::: "memory");
        __syncthreads();
        const int buf = cc & 1;
        const uint32_t Aa = aBase + (uint32_t)(buf * (128 * ROWW * 4));
        const uint32_t Ba = bBase + (uint32_t)(buf * (32 * ROWW * 4));
#pragma unroll
        for (int s = 0; s < 2; ++s) {
            unsigned bf0[4], bf1[4], af[4];
            LDSM4(bf0[0], bf0[1], bf0[2], bf0[3], Ba + s * 32);
            LDSM4(bf1[0], bf1[1], bf1[2], bf1[3], Ba + s * 32 + 16);
            LDSM4(af[0], af[1], af[2], af[3], Aa + s * 32);
#pragma unroll
            for (int j = 0; j < 4; ++j) {
                unsigned bb[2] = { bf0[j], bf1[j] };
                mma16816(acc[j], af, bb);
            }
        }
        __syncthreads();
        if (cc + 2 < 8) SCPA(cc + 2, buf);
    }
#undef SCPA

    const int q = lane >> 2, c2 = lane & 3;
    const int m0 = mt * 128 + w * 16 + q;
#pragma unroll
    for (int j = 0; j < 4; ++j) {
        const int n = j * 8 + 2 * c2;
        atomicAdd(&S[m0 * 32 + n],           acc[j][0]);
        atomicAdd(&S[m0 * 32 + n + 1],       acc[j][1]);
        atomicAdd(&S[(m0 + 8) * 32 + n],     acc[j][2]);
        atomicAdd(&S[(m0 + 8) * 32 + n + 1], acc[j][3]);
    }
}

// ------------------------- finish: sigmoid + probs + fc + ctx -------------------------
__global__ void __launch_bounds__(256) finish_kernel(
    const float* __restrict__ w_fc1, const float* __restrict__ b_fc1,
    const float* __restrict__ w_fc2, const float* __restrict__ b_fc2,
    float* __restrict__ out)
{
    __shared__ float ps[32];
    __shared__ float red[8];
    __shared__ float sr1;
    const int tid = threadIdx.x;
    const int lane = tid & 31, w = tid >> 5;

    float* out_ctx2   = out;
    float* out_probs2 = out + (size_t)N1 * D;
    float* out_ctx1   = out + (size_t)N1 * D + N1 * N2;
    float* out_probs1 = out + (size_t)N1 * D + N1 * N2 + (size_t)N2 * D;

    if (blockIdx.x < N1) {
        const int m = blockIdx.x;
        if (tid < N2) {
            float s = gS[0][m * 32 + tid];
            float pr = 1.f / (1.f + expf(-s * SCALE));
            ps[tid] = pr;
            out_probs2[(size_t)m * N2 + tid] = pr;
        }
        __syncthreads();
        float r2 = 0.f;
#pragma unroll
        for (int n = 0; n < N2; ++n) r2 += ps[n] * w_fc2[n];
        const float bf2 = b_fc2[0];
        for (int dd = tid; dd < D; dd += 256)
            out_ctx2[(size_t)m * D + dd] = g_v1[(size_t)m * D + dd] * r2 + bf2;
    } else {
        const int t = blockIdx.x - N1;
        float acc = 0.f;
        if (tid < N1) {
            float s = gS[1][tid * 32 + t];
            float pr = 1.f / (1.f + expf(-s * SCALE));
            out_probs1[(size_t)t * N1 + tid] = pr;
            acc = pr * w_fc1[tid];
        }
#pragma unroll
        for (int o = 16; o; o >>= 1) acc += __shfl_xor_sync(0xffffffffu, acc, o);
        if (lane == 0) red[w] = acc;
        __syncthreads();
        if (tid == 0) {
            float s = 0.f;
#pragma unroll
            for (int ww = 0; ww < 8; ++ww) s += red[ww];
            sr1 = s;
        }
        __syncthreads();
        const float r1 = sr1;
        const float bf1 = b_fc1[0];
        for (int dd = tid; dd < D; dd += 256)
            out_ctx1[(size_t)t * D + dd] = g_v2[(size_t)t * D + dd] * r1 + bf1;
    }
}

// ------------------------- launch -------------------------
extern "C" void kernel_launch(void* const* d_in, const int* in_sizes, int n_in,
                              void* d_out, int out_size)
{
    const float* x1  = (const float*)d_in[0];
    const float* x2  = (const float*)d_in[1];
    const float* Wq1 = (const float*)d_in[2];
    const float* bq1 = (const float*)d_in[3];
    const float* Wk1 = (const float*)d_in[4];
    const float* bk1 = (const float*)d_in[5];
    const float* Wv1 = (const float*)d_in[6];
    const float* bv1 = (const float*)d_in[7];
    const float* Wq2 = (const float*)d_in[8];
    const float* bq2 = (const float*)d_in[9];
    const float* Wk2 = (const float*)d_in[10];
    const float* bk2 = (const float*)d_in[11];
    const float* Wv2 = (const float*)d_in[12];
    const float* bv2 = (const float*)d_in[13];
    const float* wf1 = (const float*)d_in[14];
    const float* bf1 = (const float*)d_in[15];
    const float* wf2 = (const float*)d_in[16];
    const float* bf2 = (const float*)d_in[17];
    float* out = (float*)d_out;

    static int smem_set = 0;
    if (!smem_set) {
        cudaFuncSetAttribute(proj_kernel, cudaFuncAttributeMaxDynamicSharedMemorySize, PROJ_SMEM);
        smem_set = 1;
    }

    prep_kernel<<<384, 256>>>(x1, x2);
    zk_kernel<<<64, 256>>>();
    proj_kernel<<<144, 512, PROJ_SMEM>>>(Wq1, Wk1, Wv1, Wq2, Wk2, Wv2,
                                         bq1, bk1, bv1, bq2, bk2, bv2);
    smma_kernel<<<32, 256>>>();
    finish_kernel<<<277, 256>>>(wf1, bf1, wf2, bf2, out);
}

// round 11
// speedup vs baseline: 1.6571x; 1.0516x over previous
#include <cuda_runtime.h>
#include <cuda_fp16.h>
#include <math.h>
#include <stdint.h>

#define D  2048
#define N1 250
#define N2 27
#define SCALE 0.022097086912079608f   // 1/sqrt(2048)

// ------------------------- scratch -------------------------
__device__ __half g_xh[384 * D];                 // rows 0-255: x1 (padded), 256-287: x2, rest pad
__device__ float g_q1[N1 * D], g_k1[N1 * D], g_v1[N1 * D];
__device__ float g_q2[N2 * D], g_k2[N2 * D], g_v2[N2 * D];
__device__ __half g_q1h[256 * D], g_k1h[256 * D];   // fp16 copies (pad rows stay 0)
__device__ __half g_q2h[32 * D],  g_k2h[32 * D];
__device__ float gS[2][256 * 32];                // [0]=S2 (q1.k2T), [1]=S1T (k1.q2T)

// ------------------------- prep: fp32 -> fp16 activations (+ zero gS) -------------------------
__global__ void __launch_bounds__(256) prep_kernel(const float* __restrict__ x1,
                                                   const float* __restrict__ x2)
{
    if (blockIdx.x >= 384) {                     // blocks 384..447 zero gS (16384 floats)
        int i = (blockIdx.x - 384) * 256 + threadIdx.x;
        ((float*)gS)[i] = 0.f;
        return;
    }
    int t = blockIdx.x * 256 + threadIdx.x;      // 384*256 threads, 8 elems each
    int row = t >> 8;
    int c0 = (t & 255) * 8;
    float4 f0 = make_float4(0.f, 0.f, 0.f, 0.f), f1 = f0;
    if (row < 256) {
        if (row < N1) {
            const float4* s = (const float4*)(x1 + (size_t)row * D + c0);
            f0 = s[0]; f1 = s[1];
        }
    } else {
        int r2 = row - 256;
        if (r2 < N2) {
            const float4* s = (const float4*)(x2 + (size_t)r2 * D + c0);
            f0 = s[0]; f1 = s[1];
        }
    }
    __half2 h0 = __float22half2_rn(make_float2(f0.x, f0.y));
    __half2 h1 = __float22half2_rn(make_float2(f0.z, f0.w));
    __half2 h2 = __float22half2_rn(make_float2(f1.x, f1.y));
    __half2 h3 = __float22half2_rn(make_float2(f1.z, f1.w));
    uint4 w;
    w.x = *(unsigned*)&h0; w.y = *(unsigned*)&h1;
    w.z = *(unsigned*)&h2; w.w = *(unsigned*)&h3;
    *(uint4*)(g_xh + (size_t)row * D + c0) = w;
}

// ------------------------- projection GEMM (fp16 mma.sync, fp32 accum) -------------------------
#define ROWW 20                      // padded row stride in words (32 f16 + 8 pad) = 80 B
#define ABUF_WORDS (128 * ROWW)      // 10240 B
#define BBUF_WORDS (128 * ROWW)
#define ABUF_BYTES (ABUF_WORDS * 4)
#define BBUF_BYTES (BBUF_WORDS * 4)
#define SUB_WORDS (4 * ABUF_WORDS + 3 * BBUF_WORDS)   // 17920 words
#define PROJ_SMEM (2 * SUB_WORDS * 4)                 // 143360 B

__device__ __forceinline__ void mma16816(float* c, const unsigned* a, const unsigned* b) {
    asm volatile(
        "mma.sync.aligned.m16n8k16.row.col.f32.f16.f16.f32 "
        "{%0,%1,%2,%3},{%4,%5,%6,%7},{%8,%9},{%0,%1,%2,%3};"
        : "+f"(c[0]), "+f"(c[1]), "+f"(c[2]), "+f"(c[3])
        : "r"(a[0]), "r"(a[1]), "r"(a[2]), "r"(a[3]), "r"(b[0]), "r"(b[1]));
}
#define LDSM4(r0, r1, r2, r3, addr)                                      \
    asm volatile("ldmatrix.sync.aligned.m8n8.x4.shared.b16 {%0,%1,%2,%3}, [%4];" \
                 : "=r"(r0), "=r"(r1), "=r"(r2), "=r"(r3) : "r"(addr))

extern __shared__ unsigned proj_smem[];

__global__ void __launch_bounds__(512, 1) proj_kernel(
    const float* __restrict__ Wq1, const float* __restrict__ Wk1, const float* __restrict__ Wv1,
    const float* __restrict__ Wq2, const float* __restrict__ Wk2, const float* __restrict__ Wv2,
    const float* __restrict__ bq1, const float* __restrict__ bk1, const float* __restrict__ bv1,
    const float* __restrict__ bq2, const float* __restrict__ bk2, const float* __restrict__ bv2)
{
    const int tid = threadIdx.x;
    const int sub = tid >> 8;            // 0 or 1
    const int st  = tid & 255;           // thread id within sub
    const int lane = tid & 31;
    const int wid8 = (tid >> 5) & 7;     // warp id within sub

    // ---- tile decode ----
    const float* W; const float* bias; float* Cout; __half* Couth;
    int aRow0, rowBase, Mv, nb;
    {
        int b = blockIdx.x;
        if (b < 96) {
            int p = b >> 5, mt = (b >> 4) & 1, nt = b & 15;
            nb = nt * 128; aRow0 = mt * 128; rowBase = mt * 128; Mv = N1;
            W    = (p == 0) ? Wq1 : ((p == 1) ? Wk1 : Wv1);
            bias = (p == 0) ? bq1 : ((p == 1) ? bk1 : bv1);
            Cout = (p == 0) ? g_q1 : ((p == 1) ? g_k1 : g_v1);
            Couth = (p == 0) ? g_q1h : ((p == 1) ? g_k1h : (__half*)0);
        } else {
            int b2 = b - 96, p = b2 >> 4, nt = b2 & 15;
            nb = nt * 128; aRow0 = 256; rowBase = 0; Mv = N2;
            W    = (p == 0) ? Wq2 : ((p == 1) ? Wk2 : Wv2);
            bias = (p == 0) ? bq2 : ((p == 1) ? bk2 : bv2);
            Cout = (p == 0) ? g_q2 : ((p == 1) ? g_k2 : g_v2);
            Couth = (p == 0) ? g_q2h : ((p == 1) ? g_k2h : (__half*)0);
        }
    }

    unsigned* Asm = proj_smem + sub * SUB_WORDS;     // 4 A stages
    unsigned* Bsm = Asm + 4 * ABUF_WORDS;            // 3 B stages
    uint32_t AsmU32, BsmU32;
    asm("{ .reg .u64 t; cvta.to.shared.u64 t, %1; cvt.u32.u64 %0, t; }" : "=r"(AsmU32) : "l"(Asm));
    asm("{ .reg .u64 t; cvta.to.shared.u64 t, %1; cvt.u32.u64 %0, t; }" : "=r"(BsmU32) : "l"(Bsm));

    // ---- producer addressing (within sub) ----
    const int rB = st >> 1, hB = st & 1;             // B: 2 thr/row, 16 fp32
    const int rA = st & 127, hA = (st >> 7) & 1;     // A: 2 thr/row, 16 fp16
    const float*  bp = W + (size_t)(nb + rB) * D + hB * 16;
    const __half* ap = g_xh + (size_t)(aRow0 + rA) * D + hA * 16;
    unsigned* bDst = Bsm + rB * ROWW + hB * 8;
    uint32_t aDstBase;
    {
        unsigned* p0 = Asm + rA * ROWW + hA * 8;
        asm("{ .reg .u64 t; cvta.to.shared.u64 t, %1; cvt.u32.u64 %0, t; }"
            : "=r"(aDstBase) : "l"(p0));
    }

    // ---- consumer addressing (ldmatrix lane offsets, byte units) ----
    const int warpM = (wid8 & 1) * 64;
    const int warpN = (wid8 >> 1) * 32;
    const int q = lane >> 2, c = lane & 3;
    const uint32_t aoff = (uint32_t)(((lane & 7) + ((lane >> 3) & 1) * 8) * 80 + (lane >> 4) * 16);
    const uint32_t boff = (uint32_t)(lane * 80);
    const uint32_t aBase0 = AsmU32 + (uint32_t)(warpM * 80) + aoff;
    const uint32_t bBase0 = BsmU32 + (uint32_t)(warpN * 80) + boff;

    float acc[4][4][4];
#pragma unroll
    for (int i = 0; i < 4; ++i)
#pragma unroll
        for (int j = 0; j < 4; ++j)
#pragma unroll
            for (int r = 0; r < 4; ++r) acc[i][j][r] = 0.f;

    float4 s0, s1, s2, s3;      // single B staging set

#define BAR_SUB() asm volatile("bar.sync %0, %1;" :: "r"(sub + 1), "r"(256) : "memory")

#define LDGB(g) do {                                                     \
        const float4* bp4 = (const float4*)(bp + (g) * 32);              \
        s0 = bp4[0]; s1 = bp4[1]; s2 = bp4[2]; s3 = bp4[3];              \
    } while (0)

#define STSB(buf) do {                                                   \
        __half2 p0 = __float22half2_rn(make_float2(s0.x, s0.y));         \
        __half2 p1 = __float22half2_rn(make_float2(s0.z, s0.w));         \
        __half2 p2 = __float22half2_rn(make_float2(s1.x, s1.y));         \
        __half2 p3 = __float22half2_rn(make_float2(s1.z, s1.w));         \
        __half2 p4 = __float22half2_rn(make_float2(s2.x, s2.y));         \
        __half2 p5 = __float22half2_rn(make_float2(s2.z, s2.w));         \
        __half2 p6 = __float22half2_rn(make_float2(s3.x, s3.y));         \
        __half2 p7 = __float22half2_rn(make_float2(s3.z, s3.w));         \
        uint4* bd = (uint4*)(bDst + (buf) * BBUF_WORDS);                 \
        bd[0] = make_uint4(*(unsigned*)&p0, *(unsigned*)&p1,             \
                           *(unsigned*)&p2, *(unsigned*)&p3);            \
        bd[1] = make_uint4(*(unsigned*)&p4, *(unsigned*)&p5,             \
                           *(unsigned*)&p6, *(unsigned*)&p7);            \
    } while (0)

#define CPA(ia) do {                                                     \
        uint32_t dst = aDstBase + (unsigned)(((ia) & 3) * ABUF_WORDS) * 4u; \
        const __half* src = ap + (size_t)(2 * (ia) + sub) * 32;          \
        asm volatile("cp.async.ca.shared.global [%0], [%1], 16;"         \
                     :: "r"(dst), "l"(src));                             \
        asm volatile("cp.async.ca.shared.global [%0], [%1], 16;"         \
                     :: "r"(dst + 16), "l"(src + 8));                    \
        asm volatile("cp.async.commit_group;" ::: "memory");             \
    } while (0)

#define COMPUTE(as, bs) do {                                             \
        const uint32_t Aa = aBase0 + (uint32_t)((as) * ABUF_BYTES);      \
        const uint32_t Ba = bBase0 + (uint32_t)((bs) * BBUF_BYTES);      \
        _Pragma("unroll")                                                \
        for (int s = 0; s < 2; ++s) {                                    \
            unsigned bf[4][2];                                           \
            LDSM4(bf[0][0], bf[1][0], bf[2][0], bf[3][0], Ba + s * 32);  \
            LDSM4(bf[0][1], bf[1][1], bf[2][1], bf[3][1], Ba + s * 32 + 16); \
            _Pragma("unroll")                                            \
            for (int i = 0; i < 4; ++i) {                                \
                unsigned af[4];                                          \
                LDSM4(af[0], af[1], af[2], af[3], Aa + i * (16 * 80) + s * 32); \
                _Pragma("unroll")                                        \
                for (int j = 0; j < 4; ++j)                              \
                    mma16816(acc[i][j], af, bf[j]);                      \
            }                                                            \
        }                                                                \
    } while (0)

    // ---- prologue ----
    CPA(0); CPA(1); CPA(2);
    LDGB(sub);            // B for sub-iter 0 (global chunk = sub)
    STSB(0);
    LDGB(2 + sub);        // B for sub-iter 1

    int bcur = 0;
#pragma unroll 1
    for (int i = 0; i < 32; ++i) {
        int bnext = bcur + 1; if (bnext == 3) bnext = 0;
        if (i + 1 < 32) STSB(bnext);                 // stage B(i+1)
        if (i + 2 < 32) LDGB(2 * (i + 2) + sub);     // fetch B(i+2)
        if (i < 30)      asm volatile("cp.async.wait_group 2;" ::: "memory");
        else if (i == 30) asm volatile("cp.async.wait_group 1;" ::: "memory");
        else             asm volatile("cp.async.wait_group 0;" ::: "memory");
        BAR_SUB();
        if (i + 3 < 32) CPA(i + 3);                  // safe: post-barrier
        COMPUTE(i & 3, bcur);
        bcur = bnext;
    }

    // ---- reduction (sub1 acc -> smem, sub0 adds) + epilogue ----
    __syncthreads();
    float* red = (float*)proj_smem;                  // 128 x 132 fp32 pitch
    if (sub == 1) {
#pragma unroll
        for (int i = 0; i < 4; ++i) {
            const int r0 = warpM + i * 16 + q;
#pragma unroll
            for (int j = 0; j < 4; ++j) {
                const int col = warpN + j * 8 + 2 * c;
                *(float2*)(red + r0 * 132 + col)       = make_float2(acc[i][j][0], acc[i][j][1]);
                *(float2*)(red + (r0 + 8) * 132 + col) = make_float2(acc[i][j][2], acc[i][j][3]);
            }
        }
    }
    __syncthreads();
    if (sub == 0) {
#pragma unroll
        for (int i = 0; i < 4; ++i) {
            const int r0 = rowBase + warpM + i * 16 + q;
            const int rl = warpM + i * 16 + q;
            const bool ok0 = r0 < Mv, ok1 = (r0 + 8) < Mv;
#pragma unroll
            for (int j = 0; j < 4; ++j) {
                const int col = nb + warpN + j * 8 + 2 * c;
                const int cl = warpN + j * 8 + 2 * c;
                const float2 bv = *(const float2*)(bias + col);
                float2 e0 = *(const float2*)(red + rl * 132 + cl);
                float2 e1 = *(const float2*)(red + (rl + 8) * 132 + cl);
                if (ok0) {
                    float2 o = make_float2(acc[i][j][0] + e0.x + bv.x,
                                           acc[i][j][1] + e0.y + bv.y);
                    *(float2*)(Cout + (size_t)r0 * D + col) = o;
                    if (Couth) {
                        __half2 h = __float22half2_rn(o);
                        *(unsigned*)(Couth + (size_t)r0 * D + col) = *(unsigned*)&h;
                    }
                }
                if (ok1) {
                    float2 o = make_float2(acc[i][j][2] + e1.x + bv.x,
                                           acc[i][j][3] + e1.y + bv.y);
                    *(float2*)(Cout + (size_t)(r0 + 8) * D + col) = o;
                    if (Couth) {
                        __half2 h = __float22half2_rn(o);
                        *(unsigned*)(Couth + (size_t)(r0 + 8) * D + col) = *(unsigned*)&h;
                    }
                }
            }
        }
    }
#undef BAR_SUB
#undef LDGB
#undef STSB
#undef CPA
#undef COMPUTE
}

// ------------------------- score GEMMs on tensor pipe -------------------------
// 128 CTAs x 256 thr: gemm = b>>6 (0: S2 = q1h.k2hT, 1: S1T = k1h.q2hT),
// mt = (b>>5)&1 M-tile of 128, ks = b&31 K-split of 64 (2 BK32 iterations).
__global__ void __launch_bounds__(256) smma_kernel()
{
    __shared__ unsigned As[2][128 * ROWW];
    __shared__ unsigned Bs[2][32 * ROWW];
    const int tid = threadIdx.x, lane = tid & 31, w = tid >> 5;
    const int b = blockIdx.x;
    const int gemm = b >> 6, mt = (b >> 5) & 1, ks = b & 31;
    const __half* Ah = gemm ? g_k1h : g_q1h;
    const __half* Bh = gemm ? g_q2h : g_k2h;
    float* S = gS[gemm];

    const int rA = tid & 127, hA = tid >> 7;
    const __half* apA = Ah + (size_t)(mt * 128 + rA) * D + ks * 64 + hA * 16;
    const int rB = tid >> 2, qb = tid & 3;           // tid<128 only
    const __half* apB = Bh + (size_t)rB * D + ks * 64 + qb * 8;

    uint32_t aDst, bDst, AsU, BsU;
    { unsigned* p = &As[0][rA * ROWW + hA * 8];
      asm("{ .reg .u64 t; cvta.to.shared.u64 t, %1; cvt.u32.u64 %0, t; }" : "=r"(aDst) : "l"(p)); }
    { unsigned* p = &Bs[0][rB * ROWW + qb * 4];
      asm("{ .reg .u64 t; cvta.to.shared.u64 t, %1; cvt.u32.u64 %0, t; }" : "=r"(bDst) : "l"(p)); }
    asm("{ .reg .u64 t; cvta.to.shared.u64 t, %1; cvt.u32.u64 %0, t; }" : "=r"(AsU) : "l"(&As[0][0]));
    asm("{ .reg .u64 t; cvta.to.shared.u64 t, %1; cvt.u32.u64 %0, t; }" : "=r"(BsU) : "l"(&Bs[0][0]));

    const uint32_t aoff = (uint32_t)(((lane & 7) + ((lane >> 3) & 1) * 8) * 80 + (lane >> 4) * 16);
    const uint32_t aBase = AsU + (uint32_t)(w * 16 * 80) + aoff;
    const uint32_t bBase = BsU + (uint32_t)(lane * 80);

    float acc[4][4];
#pragma unroll
    for (int j = 0; j < 4; ++j)
#pragma unroll
        for (int r = 0; r < 4; ++r) acc[j][r] = 0.f;

#define SCPA(cc, buf) do {                                               \
        uint32_t da = aDst + (buf) * (128 * ROWW * 4);                   \
        const __half* sa = apA + (cc) * 32;                              \
        asm volatile("cp.async.ca.shared.global [%0], [%1], 16;" :: "r"(da), "l"(sa)); \
        asm volatile("cp.async.ca.shared.global [%0], [%1], 16;" :: "r"(da + 16), "l"(sa + 8)); \
        if (tid < 128) {                                                 \
            uint32_t db = bDst + (buf) * (32 * ROWW * 4);                \
            const __half* sb = apB + (cc) * 32;                          \
            asm volatile("cp.async.ca.shared.global [%0], [%1], 16;" :: "r"(db), "l"(sb)); \
        }                                                                \
        asm volatile("cp.async.commit_group;" ::: "memory");             \
    } while (0)

    SCPA(0, 0); SCPA(1, 1);
#pragma unroll
    for (int cc = 0; cc < 2; ++cc) {
        if (cc == 0) asm volatile("cp.async.wait_group 1;" ::: "memory");
        else         asm volatile("cp.async.wait_group 0;" ::: "memory");
        __syncthreads();
        const int buf = cc & 1;
        const uint32_t Aa = aBase + (uint32_t)(buf * (128 * ROWW * 4));
        const uint32_t Ba = bBase + (uint32_t)(buf * (32 * ROWW * 4));
#pragma unroll
        for (int s = 0; s < 2; ++s) {
            unsigned bf0[4], bf1[4], af[4];
            LDSM4(bf0[0], bf0[1], bf0[2], bf0[3], Ba + s * 32);
            LDSM4(bf1[0], bf1[1], bf1[2], bf1[3], Ba + s * 32 + 16);
            LDSM4(af[0], af[1], af[2], af[3], Aa + s * 32);
#pragma unroll
            for (int j = 0; j < 4; ++j) {
                unsigned bb[2] = { bf0[j], bf1[j] };
                mma16816(acc[j], af, bb);
            }
        }
        __syncthreads();
    }
#undef SCPA

    const int q = lane >> 2, c2 = lane & 3;
    const int m0 = mt * 128 + w * 16 + q;
#pragma unroll
    for (int j = 0; j < 4; ++j) {
        const int n = j * 8 + 2 * c2;
        atomicAdd(&S[m0 * 32 + n],           acc[j][0]);
        atomicAdd(&S[m0 * 32 + n + 1],       acc[j][1]);
        atomicAdd(&S[(m0 + 8) * 32 + n],     acc[j][2]);
        atomicAdd(&S[(m0 + 8) * 32 + n + 1], acc[j][3]);
    }
}

// ------------------------- finish: sigmoid + probs + fc + ctx -------------------------
__global__ void __launch_bounds__(256) finish_kernel(
    const float* __restrict__ w_fc1, const float* __restrict__ b_fc1,
    const float* __restrict__ w_fc2, const float* __restrict__ b_fc2,
    float* __restrict__ out)
{
    __shared__ float ps[32];
    __shared__ float red[8];
    __shared__ float sr1;
    const int tid = threadIdx.x;
    const int lane = tid & 31, w = tid >> 5;

    float* out_ctx2   = out;
    float* out_probs2 = out + (size_t)N1 * D;
    float* out_ctx1   = out + (size_t)N1 * D + N1 * N2;
    float* out_probs1 = out + (size_t)N1 * D + N1 * N2 + (size_t)N2 * D;

    if (blockIdx.x < N1) {
        const int m = blockIdx.x;
        if (tid < N2) {
            float s = gS[0][m * 32 + tid];
            float pr = 1.f / (1.f + expf(-s * SCALE));
            ps[tid] = pr;
            out_probs2[(size_t)m * N2 + tid] = pr;
        }
        __syncthreads();
        float r2 = 0.f;
#pragma unroll
        for (int n = 0; n < N2; ++n) r2 += ps[n] * w_fc2[n];
        const float bf2 = b_fc2[0];
        for (int dd = tid; dd < D; dd += 256)
            out_ctx2[(size_t)m * D + dd] = g_v1[(size_t)m * D + dd] * r2 + bf2;
    } else {
        const int t = blockIdx.x - N1;
        float acc = 0.f;
        if (tid < N1) {
            float s = gS[1][tid * 32 + t];
            float pr = 1.f / (1.f + expf(-s * SCALE));
            out_probs1[(size_t)t * N1 + tid] = pr;
            acc = pr * w_fc1[tid];
        }
#pragma unroll
        for (int o = 16; o; o >>= 1) acc += __shfl_xor_sync(0xffffffffu, acc, o);
        if (lane == 0) red[w] = acc;
        __syncthreads();
        if (tid == 0) {
            float s = 0.f;
#pragma unroll
            for (int ww = 0; ww < 8; ++ww) s += red[ww];
            sr1 = s;
        }
        __syncthreads();
        const float r1 = sr1;
        const float bf1 = b_fc1[0];
        for (int dd = tid; dd < D; dd += 256)
            out_ctx1[(size_t)t * D + dd] = g_v2[(size_t)t * D + dd] * r1 + bf1;
    }
}

// ------------------------- launch -------------------------
extern "C" void kernel_launch(void* const* d_in, const int* in_sizes, int n_in,
                              void* d_out, int out_size)
{
    const float* x1  = (const float*)d_in[0];
    const float* x2  = (const float*)d_in[1];
    const float* Wq1 = (const float*)d_in[2];
    const float* bq1 = (const float*)d_in[3];
    const float* Wk1 = (const float*)d_in[4];
    const float* bk1 = (const float*)d_in[5];
    const float* Wv1 = (const float*)d_in[6];
    const float* bv1 = (const float*)d_in[7];
    const float* Wq2 = (const float*)d_in[8];
    const float* bq2 = (const float*)d_in[9];
    const float* Wk2 = (const float*)d_in[10];
    const float* bk2 = (const float*)d_in[11];
    const float* Wv2 = (const float*)d_in[12];
    const float* bv2 = (const float*)d_in[13];
    const float* wf1 = (const float*)d_in[14];
    const float* bf1 = (const float*)d_in[15];
    const float* wf2 = (const float*)d_in[16];
    const float* bf2 = (const float*)d_in[17];
    float* out = (float*)d_out;

    static int smem_set = 0;
    if (!smem_set) {
        cudaFuncSetAttribute(proj_kernel, cudaFuncAttributeMaxDynamicSharedMemorySize, PROJ_SMEM);
        smem_set = 1;
    }

    prep_kernel<<<448, 256>>>(x1, x2);
    proj_kernel<<<144, 512, PROJ_SMEM>>>(Wq1, Wk1, Wv1, Wq2, Wk2, Wv2,
                                         bq1, bk1, bv1, bq2, bk2, bv2);
    smma_kernel<<<128, 256>>>();
    finish_kernel<<<277, 256>>>(wf1, bf1, wf2, bf2, out);
}

// round 13
// speedup vs baseline: 1.7039x; 1.0283x over previous
#include <cuda_runtime.h>
#include <cuda_fp16.h>
#include <math.h>
#include <stdint.h>

#define D  2048
#define N1 250
#define N2 27
#define SCALE 0.022097086912079608f   // 1/sqrt(2048)

// ------------------------- scratch -------------------------
__device__ __half g_xh[384 * D];                 // rows 0-255: x1 (padded), 256-287: x2, rest pad
__device__ float g_q1[N1 * D], g_k1[N1 * D];
__device__ __align__(16) float g_v1[N1 * D];
__device__ float g_q2[N2 * D], g_k2[N2 * D];
__device__ __align__(16) float g_v2[N2 * D];
__device__ __half g_q1h[256 * D], g_k1h[256 * D];   // fp16 copies (pad rows stay 0)
__device__ __half g_q2h[32 * D],  g_k2h[32 * D];
__device__ float gS[2][256 * 32];                // [0]=S2 (q1.k2T), [1]=S1T (k1.q2T)

// ------------------------- prep: fp32 -> fp16 activations (+ zero gS) -------------------------
__global__ void __launch_bounds__(256) prep_kernel(const float* __restrict__ x1,
                                                   const float* __restrict__ x2)
{
    if (blockIdx.x >= 384) {                     // blocks 384..447 zero gS (16384 floats)
        int i = (blockIdx.x - 384) * 256 + threadIdx.x;
        ((float*)gS)[i] = 0.f;
        return;
    }
    int t = blockIdx.x * 256 + threadIdx.x;      // 384*256 threads, 8 elems each
    int row = t >> 8;
    int c0 = (t & 255) * 8;
    float4 f0 = make_float4(0.f, 0.f, 0.f, 0.f), f1 = f0;
    if (row < 256) {
        if (row < N1) {
            const float4* s = (const float4*)(x1 + (size_t)row * D + c0);
            f0 = s[0]; f1 = s[1];
        }
    } else {
        int r2 = row - 256;
        if (r2 < N2) {
            const float4* s = (const float4*)(x2 + (size_t)r2 * D + c0);
            f0 = s[0]; f1 = s[1];
        }
    }
    __half2 h0 = __float22half2_rn(make_float2(f0.x, f0.y));
    __half2 h1 = __float22half2_rn(make_float2(f0.z, f0.w));
    __half2 h2 = __float22half2_rn(make_float2(f1.x, f1.y));
    __half2 h3 = __float22half2_rn(make_float2(f1.z, f1.w));
    uint4 w;
    w.x = *(unsigned*)&h0; w.y = *(unsigned*)&h1;
    w.z = *(unsigned*)&h2; w.w = *(unsigned*)&h3;
    *(uint4*)(g_xh + (size_t)row * D + c0) = w;
}

// ------------------------- projection GEMM (fp16 mma.sync, fp32 accum) -------------------------
#define ROWW 20                      // padded row stride in words (32 f16 + 8 pad) = 80 B
#define ABUF_WORDS (128 * ROWW)      // 10240 B
#define BBUF_WORDS (128 * ROWW)
#define ABUF_BYTES (ABUF_WORDS * 4)
#define BBUF_BYTES (BBUF_WORDS * 4)
#define SUB_WORDS (4 * ABUF_WORDS + 3 * BBUF_WORDS)   // 17920 words
#define PROJ_SMEM (2 * SUB_WORDS * 4)                 // 143360 B

__device__ __forceinline__ void mma16816(float* c, const unsigned* a, const unsigned* b) {
    asm volatile(
        "mma.sync.aligned.m16n8k16.row.col.f32.f16.f16.f32 "
        "{%0,%1,%2,%3},{%4,%5,%6,%7},{%8,%9},{%0,%1,%2,%3};"
        : "+f"(c[0]), "+f"(c[1]), "+f"(c[2]), "+f"(c[3])
        : "r"(a[0]), "r"(a[1]), "r"(a[2]), "r"(a[3]), "r"(b[0]), "r"(b[1]));
}
#define LDSM4(r0, r1, r2, r3, addr)                                      \
    asm volatile("ldmatrix.sync.aligned.m8n8.x4.shared.b16 {%0,%1,%2,%3}, [%4];" \
                 : "=r"(r0), "=r"(r1), "=r"(r2), "=r"(r3) : "r"(addr))

extern __shared__ unsigned proj_smem[];

__global__ void __launch_bounds__(512, 1) proj_kernel(
    const float* __restrict__ Wq1, const float* __restrict__ Wk1, const float* __restrict__ Wv1,
    const float* __restrict__ Wq2, const float* __restrict__ Wk2, const float* __restrict__ Wv2,
    const float* __restrict__ bq1, const float* __restrict__ bk1, const float* __restrict__ bv1,
    const float* __restrict__ bq2, const float* __restrict__ bk2, const float* __restrict__ bv2)
{
    const int tid = threadIdx.x;
    const int sub = tid >> 8;            // 0 or 1
    const int st  = tid & 255;           // thread id within sub
    const int lane = tid & 31;
    const int wid8 = (tid >> 5) & 7;     // warp id within sub

    // ---- tile decode ----
    const float* W; const float* bias; float* Cout; __half* Couth;
    int aRow0, rowBase, Mv, nb;
    {
        int b = blockIdx.x;
        if (b < 96) {
            int p = b >> 5, mt = (b >> 4) & 1, nt = b & 15;
            nb = nt * 128; aRow0 = mt * 128; rowBase = mt * 128; Mv = N1;
            W    = (p == 0) ? Wq1 : ((p == 1) ? Wk1 : Wv1);
            bias = (p == 0) ? bq1 : ((p == 1) ? bk1 : bv1);
            Cout = (p == 0) ? g_q1 : ((p == 1) ? g_k1 : g_v1);
            Couth = (p == 0) ? g_q1h : ((p == 1) ? g_k1h : (__half*)0);
        } else {
            int b2 = b - 96, p = b2 >> 4, nt = b2 & 15;
            nb = nt * 128; aRow0 = 256; rowBase = 0; Mv = N2;
            W    = (p == 0) ? Wq2 : ((p == 1) ? Wk2 : Wv2);
            bias = (p == 0) ? bq2 : ((p == 1) ? bk2 : bv2);
            Cout = (p == 0) ? g_q2 : ((p == 1) ? g_k2 : g_v2);
            Couth = (p == 0) ? g_q2h : ((p == 1) ? g_k2h : (__half*)0);
        }
    }

    unsigned* Asm = proj_smem + sub * SUB_WORDS;     // 4 A stages
    unsigned* Bsm = Asm + 4 * ABUF_WORDS;            // 3 B stages
    uint32_t AsmU32, BsmU32;
    asm("{ .reg .u64 t; cvta.to.shared.u64 t, %1; cvt.u32.u64 %0, t; }" : "=r"(AsmU32) : "l"(Asm));
    asm("{ .reg .u64 t; cvta.to.shared.u64 t, %1; cvt.u32.u64 %0, t; }" : "=r"(BsmU32) : "l"(Bsm));

    // ---- producer addressing (within sub) ----
    const int rB = st >> 1, hB = st & 1;             // B: 2 thr/row, 16 fp32
    const int rA = st & 127, hA = (st >> 7) & 1;     // A: 2 thr/row, 16 fp16
    const float*  bp = W + (size_t)(nb + rB) * D + hB * 16;
    const __half* ap = g_xh + (size_t)(aRow0 + rA) * D + hA * 16;
    unsigned* bDst = Bsm + rB * ROWW + hB * 8;
    uint32_t aDstBase;
    {
        unsigned* p0 = Asm + rA * ROWW + hA * 8;
        asm("{ .reg .u64 t; cvta.to.shared.u64 t, %1; cvt.u32.u64 %0, t; }"
            : "=r"(aDstBase) : "l"(p0));
    }

    // ---- consumer addressing (ldmatrix lane offsets, byte units) ----
    const int warpM = (wid8 & 1) * 64;
    const int warpN = (wid8 >> 1) * 32;
    const int q = lane >> 2, c = lane & 3;
    const uint32_t aoff = (uint32_t)(((lane & 7) + ((lane >> 3) & 1) * 8) * 80 + (lane >> 4) * 16);
    const uint32_t boff = (uint32_t)(lane * 80);
    const uint32_t aBase0 = AsmU32 + (uint32_t)(warpM * 80) + aoff;
    const uint32_t bBase0 = BsmU32 + (uint32_t)(warpN * 80) + boff;

    float acc[4][4][4];
#pragma unroll
    for (int i = 0; i < 4; ++i)
#pragma unroll
        for (int j = 0; j < 4; ++j)
#pragma unroll
            for (int r = 0; r < 4; ++r) acc[i][j][r] = 0.f;

    float4 s0, s1, s2, s3;      // single B staging set

#define BAR_SUB() asm volatile("bar.sync %0, %1;" :: "r"(sub + 1), "r"(256) : "memory")

#define LDGB(g) do {                                                     \
        const float4* bp4 = (const float4*)(bp + (g) * 32);              \
        s0 = bp4[0]; s1 = bp4[1]; s2 = bp4[2]; s3 = bp4[3];              \
    } while (0)

#define STSB(buf) do {                                                   \
        __half2 p0 = __float22half2_rn(make_float2(s0.x, s0.y));         \
        __half2 p1 = __float22half2_rn(make_float2(s0.z, s0.w));         \
        __half2 p2 = __float22half2_rn(make_float2(s1.x, s1.y));         \
        __half2 p3 = __float22half2_rn(make_float2(s1.z, s1.w));         \
        __half2 p4 = __float22half2_rn(make_float2(s2.x, s2.y));         \
        __half2 p5 = __float22half2_rn(make_float2(s2.z, s2.w));         \
        __half2 p6 = __float22half2_rn(make_float2(s3.x, s3.y));         \
        __half2 p7 = __float22half2_rn(make_float2(s3.z, s3.w));         \
        uint4* bd = (uint4*)(bDst + (buf) * BBUF_WORDS);                 \
        bd[0] = make_uint4(*(unsigned*)&p0, *(unsigned*)&p1,             \
                           *(unsigned*)&p2, *(unsigned*)&p3);            \
        bd[1] = make_uint4(*(unsigned*)&p4, *(unsigned*)&p5,             \
                           *(unsigned*)&p6, *(unsigned*)&p7);            \
    } while (0)

#define CPA(ia) do {                                                     \
        uint32_t dst = aDstBase + (unsigned)(((ia) & 3) * ABUF_WORDS) * 4u; \
        const __half* src = ap + (size_t)(2 * (ia) + sub) * 32;          \
        asm volatile("cp.async.ca.shared.global [%0], [%1], 16;"         \
                     :: "r"(dst), "l"(src));                             \
        asm volatile("cp.async.ca.shared.global [%0], [%1], 16;"         \
                     :: "r"(dst + 16), "l"(src + 8));                    \
        asm volatile("cp.async.commit_group;" ::: "memory");             \
    } while (0)

#define COMPUTE(as, bs) do {                                             \
        const uint32_t Aa = aBase0 + (uint32_t)((as) * ABUF_BYTES);      \
        const uint32_t Ba = bBase0 + (uint32_t)((bs) * BBUF_BYTES);      \
        _Pragma("unroll")                                                \
        for (int s = 0; s < 2; ++s) {                                    \
            unsigned bf[4][2];                                           \
            LDSM4(bf[0][0], bf[1][0], bf[2][0], bf[3][0], Ba + s * 32);  \
            LDSM4(bf[0][1], bf[1][1], bf[2][1], bf[3][1], Ba + s * 32 + 16); \
            _Pragma("unroll")                                            \
            for (int i = 0; i < 4; ++i) {                                \
                unsigned af[4];                                          \
                LDSM4(af[0], af[1], af[2], af[3], Aa + i * (16 * 80) + s * 32); \
                _Pragma("unroll")                                        \
                for (int j = 0; j < 4; ++j)                              \
                    mma16816(acc[i][j], af, bf[j]);                      \
            }                                                            \
        }                                                                \
    } while (0)

    // ---- prologue ----
    CPA(0); CPA(1); CPA(2);
    LDGB(sub);            // B for sub-iter 0 (global chunk = sub)
    STSB(0);
    LDGB(2 + sub);        // B for sub-iter 1

    int bcur = 0;
#pragma unroll 1
    for (int i = 0; i < 32; ++i) {
        int bnext = bcur + 1; if (bnext == 3) bnext = 0;
        if (i + 1 < 32) STSB(bnext);                 // stage B(i+1)
        if (i + 2 < 32) LDGB(2 * (i + 2) + sub);     // fetch B(i+2)
        if (i < 30)      asm volatile("cp.async.wait_group 2;" ::: "memory");
        else if (i == 30) asm volatile("cp.async.wait_group 1;" ::: "memory");
        else             asm volatile("cp.async.wait_group 0;" ::: "memory");
        BAR_SUB();
        if (i + 3 < 32) CPA(i + 3);                  // safe: post-barrier
        COMPUTE(i & 3, bcur);
        bcur = bnext;
    }

    // ---- reduction (sub1 acc -> smem, sub0 adds) + epilogue ----
    __syncthreads();
    float* red = (float*)proj_smem;                  // 128 x 132 fp32 pitch
    if (sub == 1) {
#pragma unroll
        for (int i = 0; i < 4; ++i) {
            const int r0 = warpM + i * 16 + q;
#pragma unroll
            for (int j = 0; j < 4; ++j) {
                const int col = warpN + j * 8 + 2 * c;
                *(float2*)(red + r0 * 132 + col)       = make_float2(acc[i][j][0], acc[i][j][1]);
                *(float2*)(red + (r0 + 8) * 132 + col) = make_float2(acc[i][j][2], acc[i][j][3]);
            }
        }
    }
    __syncthreads();
    if (sub == 0) {
#pragma unroll
        for (int i = 0; i < 4; ++i) {
            const int r0 = rowBase + warpM + i * 16 + q;
            const int rl = warpM + i * 16 + q;
            const bool ok0 = r0 < Mv, ok1 = (r0 + 8) < Mv;
#pragma unroll
            for (int j = 0; j < 4; ++j) {
                const int col = nb + warpN + j * 8 + 2 * c;
                const int cl = warpN + j * 8 + 2 * c;
                const float2 bv = *(const float2*)(bias + col);
                float2 e0 = *(const float2*)(red + rl * 132 + cl);
                float2 e1 = *(const float2*)(red + (rl + 8) * 132 + cl);
                if (ok0) {
                    float2 o = make_float2(acc[i][j][0] + e0.x + bv.x,
                                           acc[i][j][1] + e0.y + bv.y);
                    *(float2*)(Cout + (size_t)r0 * D + col) = o;
                    if (Couth) {
                        __half2 h = __float22half2_rn(o);
                        *(unsigned*)(Couth + (size_t)r0 * D + col) = *(unsigned*)&h;
                    }
                }
                if (ok1) {
                    float2 o = make_float2(acc[i][j][2] + e1.x + bv.x,
                                           acc[i][j][3] + e1.y + bv.y);
                    *(float2*)(Cout + (size_t)(r0 + 8) * D + col) = o;
                    if (Couth) {
                        __half2 h = __float22half2_rn(o);
                        *(unsigned*)(Couth + (size_t)(r0 + 8) * D + col) = *(unsigned*)&h;
                    }
                }
            }
        }
    }
#undef BAR_SUB
#undef LDGB
#undef STSB
#undef CPA
#undef COMPUTE
}

// ------------------------- score GEMMs on tensor pipe -------------------------
// 128 CTAs x 256 thr: gemm = b>>6 (0: S2 = q1h.k2hT, 1: S1T = k1h.q2hT),
// mt = (b>>5)&1 M-tile of 128, ks = b&31 K-split of 64 (2 BK32 iterations).
__global__ void __launch_bounds__(256) smma_kernel()
{
    __shared__ unsigned As[2][128 * ROWW];
    __shared__ unsigned Bs[2][32 * ROWW];
    const int tid = threadIdx.x, lane = tid & 31, w = tid >> 5;
    const int b = blockIdx.x;
    const int gemm = b >> 6, mt = (b >> 5) & 1, ks = b & 31;
    const __half* Ah = gemm ? g_k1h : g_q1h;
    const __half* Bh = gemm ? g_q2h : g_k2h;
    float* S = gS[gemm];

    const int rA = tid & 127, hA = tid >> 7;
    const __half* apA = Ah + (size_t)(mt * 128 + rA) * D + ks * 64 + hA * 16;
    const int rB = tid >> 2, qb = tid & 3;           // tid<128 only
    const __half* apB = Bh + (size_t)rB * D + ks * 64 + qb * 8;

    uint32_t aDst, bDst, AsU, BsU;
    { unsigned* p = &As[0][rA * ROWW + hA * 8];
      asm("{ .reg .u64 t; cvta.to.shared.u64 t, %1; cvt.u32.u64 %0, t; }" : "=r"(aDst) : "l"(p)); }
    { unsigned* p = &Bs[0][rB * ROWW + qb * 4];
      asm("{ .reg .u64 t; cvta.to.shared.u64 t, %1; cvt.u32.u64 %0, t; }" : "=r"(bDst) : "l"(p)); }
    asm("{ .reg .u64 t; cvta.to.shared.u64 t, %1; cvt.u32.u64 %0, t; }" : "=r"(AsU) : "l"(&As[0][0]));
    asm("{ .reg .u64 t; cvta.to.shared.u64 t, %1; cvt.u32.u64 %0, t; }" : "=r"(BsU) : "l"(&Bs[0][0]));

    const uint32_t aoff = (uint32_t)(((lane & 7) + ((lane >> 3) & 1) * 8) * 80 + (lane >> 4) * 16);
    const uint32_t aBase = AsU + (uint32_t)(w * 16 * 80) + aoff;
    const uint32_t bBase = BsU + (uint32_t)(lane * 80);

    float acc[4][4];
#pragma unroll
    for (int j = 0; j < 4; ++j)
#pragma unroll
        for (int r = 0; r < 4; ++r) acc[j][r] = 0.f;

#define SCPA(cc, buf) do {                                               \
        uint32_t da = aDst + (buf) * (128 * ROWW * 4);                   \
        const __half* sa = apA + (cc) * 32;                              \
        asm volatile("cp.async.ca.shared.global [%0], [%1], 16;" :: "r"(da), "l"(sa)); \
        asm volatile("cp.async.ca.shared.global [%0], [%1], 16;" :: "r"(da + 16), "l"(sa + 8)); \
        if (tid < 128) {                                                 \
            uint32_t db = bDst + (buf) * (32 * ROWW * 4);                \
            const __half* sb = apB + (cc) * 32;                          \
            asm volatile("cp.async.ca.shared.global [%0], [%1], 16;" :: "r"(db), "l"(sb)); \
        }                                                                \
        asm volatile("cp.async.commit_group;" ::: "memory");             \
    } while (0)

    SCPA(0, 0); SCPA(1, 1);
#pragma unroll
    for (int cc = 0; cc < 2; ++cc) {
        if (cc == 0) asm volatile("cp.async.wait_group 1;" ::: "memory");
        else         asm volatile("cp.async.wait_group 0;" ::: "memory");
        __syncthreads();
        const int buf = cc & 1;
        const uint32_t Aa = aBase + (uint32_t)(buf * (128 * ROWW * 4));
        const uint32_t Ba = bBase + (uint32_t)(buf * (32 * ROWW * 4));
#pragma unroll
        for (int s = 0; s < 2; ++s) {
            unsigned bf0[4], bf1[4], af[4];
            LDSM4(bf0[0], bf0[1], bf0[2], bf0[3], Ba + s * 32);
            LDSM4(bf1[0], bf1[1], bf1[2], bf1[3], Ba + s * 32 + 16);
            LDSM4(af[0], af[1], af[2], af[3], Aa + s * 32);
#pragma unroll
            for (int j = 0; j < 4; ++j) {
                unsigned bb[2] = { bf0[j], bf1[j] };
                mma16816(acc[j], af, bb);
            }
        }
        __syncthreads();
    }
#undef SCPA

    const int q = lane >> 2, c2 = lane & 3;
    const int m0 = mt * 128 + w * 16 + q;
#pragma unroll
    for (int j = 0; j < 4; ++j) {
        const int n = j * 8 + 2 * c2;
        atomicAdd(&S[m0 * 32 + n],           acc[j][0]);
        atomicAdd(&S[m0 * 32 + n + 1],       acc[j][1]);
        atomicAdd(&S[(m0 + 8) * 32 + n],     acc[j][2]);
        atomicAdd(&S[(m0 + 8) * 32 + n + 1], acc[j][3]);
    }
}

// ------------------------- finish: sigmoid + probs + fc + ctx -------------------------
// 554 blocks: b<500 -> ctx2/probs2 (m = b>>1, half = b&1); else ctx1/probs1
// (t = (b-500)>>1, half = (b-500)&1). Each block streams half a row.
__global__ void __launch_bounds__(256) finish_kernel(
    const float* __restrict__ w_fc1, const float* __restrict__ b_fc1,
    const float* __restrict__ w_fc2, const float* __restrict__ b_fc2,
    float* __restrict__ out)
{
    __shared__ float ps[32];
    __shared__ float red[8];
    const int tid = threadIdx.x;
    const int lane = tid & 31, w = tid >> 5;

    float* out_ctx2   = out;                                  // 16B-aligned
    float* out_probs2 = out + (size_t)N1 * D;
    float* out_ctx1   = out + (size_t)N1 * D + N1 * N2;       // 8B-aligned ONLY
    float* out_probs1 = out + (size_t)N1 * D + N1 * N2 + (size_t)N2 * D;

    if (blockIdx.x < 2 * N1) {
        const int m = blockIdx.x >> 1;
        const int half = blockIdx.x & 1;
        if (tid < N2) {
            float s = gS[0][m * 32 + tid];
            float pr = 1.f / (1.f + expf(-s * SCALE));
            ps[tid] = pr;
            if (half == 0) out_probs2[(size_t)m * N2 + tid] = pr;
        }
        __syncthreads();
        float r2 = 0.f;
#pragma unroll
        for (int n = 0; n < N2; ++n) r2 += ps[n] * w_fc2[n];
        const float bf2 = b_fc2[0];
        const int o4 = half * 256 + tid;             // float4 index into row
        float4 v = *(const float4*)(g_v1 + (size_t)m * D + o4 * 4);
        float4 o = make_float4(v.x * r2 + bf2, v.y * r2 + bf2,
                               v.z * r2 + bf2, v.w * r2 + bf2);
        *(float4*)(out_ctx2 + (size_t)m * D + o4 * 4) = o;
    } else {
        const int j = blockIdx.x - 2 * N1;
        const int t = j >> 1;
        const int half = j & 1;
        float acc = 0.f;
        if (tid < N1) {
            float s = gS[1][tid * 32 + t];
            float pr = 1.f / (1.f + expf(-s * SCALE));
            if (half == 0) out_probs1[(size_t)t * N1 + tid] = pr;
            acc = pr * w_fc1[tid];
        }
#pragma unroll
        for (int o = 16; o; o >>= 1) acc += __shfl_xor_sync(0xffffffffu, acc, o);
        if (lane == 0) red[w] = acc;
        __syncthreads();
        float r1 = 0.f;
#pragma unroll
        for (int ww = 0; ww < 8; ++ww) r1 += red[ww];
        const float bf1 = b_fc1[0];
        const int o4 = half * 256 + tid;
        float4 v = *(const float4*)(g_v2 + (size_t)t * D + o4 * 4);
        // out_ctx1 is only 8-byte aligned (offset N1*D + N1*N2 = 2 mod 4 floats):
        // store as two float2 (8B-aligned addresses).
        float* dst = out_ctx1 + (size_t)t * D + o4 * 4;
        *(float2*)(dst)     = make_float2(v.x * r1 + bf1, v.y * r1 + bf1);
        *(float2*)(dst + 2) = make_float2(v.z * r1 + bf1, v.w * r1 + bf1);
    }
}

// ------------------------- launch -------------------------
extern "C" void kernel_launch(void* const* d_in, const int* in_sizes, int n_in,
                              void* d_out, int out_size)
{
    const float* x1  = (const float*)d_in[0];
    const float* x2  = (const float*)d_in[1];
    const float* Wq1 = (const float*)d_in[2];
    const float* bq1 = (const float*)d_in[3];
    const float* Wk1 = (const float*)d_in[4];
    const float* bk1 = (const float*)d_in[5];
    const float* Wv1 = (const float*)d_in[6];
    const float* bv1 = (const float*)d_in[7];
    const float* Wq2 = (const float*)d_in[8];
    const float* bq2 = (const float*)d_in[9];
    const float* Wk2 = (const float*)d_in[10];
    const float* bk2 = (const float*)d_in[11];
    const float* Wv2 = (const float*)d_in[12];
    const float* bv2 = (const float*)d_in[13];
    const float* wf1 = (const float*)d_in[14];
    const float* bf1 = (const float*)d_in[15];
    const float* wf2 = (const float*)d_in[16];
    const float* bf2 = (const float*)d_in[17];
    float* out = (float*)d_out;

    static int smem_set = 0;
    if (!smem_set) {
        cudaFuncSetAttribute(proj_kernel, cudaFuncAttributeMaxDynamicSharedMemorySize, PROJ_SMEM);
        smem_set = 1;
    }

    prep_kernel<<<448, 256>>>(x1, x2);
    proj_kernel<<<144, 512, PROJ_SMEM>>>(Wq1, Wk1, Wv1, Wq2, Wk2, Wv2,
                                         bq1, bk1, bv1, bq2, bk2, bv2);
    smma_kernel<<<128, 256>>>();
    finish_kernel<<<2 * N1 + 2 * N2, 256>>>(wf1, bf1, wf2, bf2, out);
}

// round 14
// speedup vs baseline: 1.7591x; 1.0324x over previous
#include <cuda_runtime.h>
#include <cuda_fp16.h>
#include <math.h>
#include <stdint.h>

#define D  2048
#define N1 250
#define N2 27
#define SCALE 0.022097086912079608f   // 1/sqrt(2048)

// ------------------------- scratch -------------------------
__device__ __half g_xh[384 * D];                 // rows 0-255: x1 (padded), 256-287: x2, rest pad
__device__ __align__(16) float g_v1[N1 * D];
__device__ __align__(16) float g_v2[N2 * D];
__device__ __half g_q1h[256 * D], g_k1h[256 * D];   // fp16 copies (pad rows stay 0)
__device__ __half g_q2h[32 * D],  g_k2h[32 * D];
__device__ float gS[2][256 * 32];                // [0]=S2 (q1.k2T), [1]=S1T (k1.q2T)

// ------------------------- prep: fp32 -> fp16 activations (+ zero gS) -------------------------
__global__ void __launch_bounds__(256) prep_kernel(const float* __restrict__ x1,
                                                   const float* __restrict__ x2)
{
    if (blockIdx.x >= 384) {                     // blocks 384..447 zero gS (16384 floats)
        int i = (blockIdx.x - 384) * 256 + threadIdx.x;
        ((float*)gS)[i] = 0.f;
        return;
    }
    int t = blockIdx.x * 256 + threadIdx.x;      // 384*256 threads, 8 elems each
    int row = t >> 8;
    int c0 = (t & 255) * 8;
    float4 f0 = make_float4(0.f, 0.f, 0.f, 0.f), f1 = f0;
    if (row < 256) {
        if (row < N1) {
            const float4* s = (const float4*)(x1 + (size_t)row * D + c0);
            f0 = s[0]; f1 = s[1];
        }
    } else {
        int r2 = row - 256;
        if (r2 < N2) {
            const float4* s = (const float4*)(x2 + (size_t)r2 * D + c0);
            f0 = s[0]; f1 = s[1];
        }
    }
    __half2 h0 = __float22half2_rn(make_float2(f0.x, f0.y));
    __half2 h1 = __float22half2_rn(make_float2(f0.z, f0.w));
    __half2 h2 = __float22half2_rn(make_float2(f1.x, f1.y));
    __half2 h3 = __float22half2_rn(make_float2(f1.z, f1.w));
    uint4 w;
    w.x = *(unsigned*)&h0; w.y = *(unsigned*)&h1;
    w.z = *(unsigned*)&h2; w.w = *(unsigned*)&h3;
    *(uint4*)(g_xh + (size_t)row * D + c0) = w;
}

// ------------------------- projection GEMM (fp16 mma.sync, fp32 accum) -------------------------
#define ROWW 20                      // padded row stride in words (32 f16 + 8 pad) = 80 B
#define ABUF_WORDS (128 * ROWW)      // 10240 B
#define BBUF_WORDS (128 * ROWW)
#define ABUF_BYTES (ABUF_WORDS * 4)
#define BBUF_BYTES (BBUF_WORDS * 4)
#define SUB_WORDS (4 * ABUF_WORDS + 3 * BBUF_WORDS)   // 17920 words
#define PROJ_SMEM (2 * SUB_WORDS * 4)                 // 143360 B

__device__ __forceinline__ void mma16816(float* c, const unsigned* a, const unsigned* b) {
    asm volatile(
        "mma.sync.aligned.m16n8k16.row.col.f32.f16.f16.f32 "
        "{%0,%1,%2,%3},{%4,%5,%6,%7},{%8,%9},{%0,%1,%2,%3};"
        : "+f"(c[0]), "+f"(c[1]), "+f"(c[2]), "+f"(c[3])
        : "r"(a[0]), "r"(a[1]), "r"(a[2]), "r"(a[3]), "r"(b[0]), "r"(b[1]));
}
#define LDSM4(r0, r1, r2, r3, addr)                                      \
    asm volatile("ldmatrix.sync.aligned.m8n8.x4.shared.b16 {%0,%1,%2,%3}, [%4];" \
                 : "=r"(r0), "=r"(r1), "=r"(r2), "=r"(r3) : "r"(addr))

extern __shared__ unsigned proj_smem[];

__global__ void __launch_bounds__(512, 1) proj_kernel(
    const float* __restrict__ Wq1, const float* __restrict__ Wk1, const float* __restrict__ Wv1,
    const float* __restrict__ Wq2, const float* __restrict__ Wk2, const float* __restrict__ Wv2,
    const float* __restrict__ bq1, const float* __restrict__ bk1, const float* __restrict__ bv1,
    const float* __restrict__ bq2, const float* __restrict__ bk2, const float* __restrict__ bv2)
{
    const int tid = threadIdx.x;
    const int sub = tid >> 8;            // 0 or 1
    const int st  = tid & 255;           // thread id within sub
    const int lane = tid & 31;
    const int wid8 = (tid >> 5) & 7;     // warp id within sub

    // ---- tile decode ----
    const float* W; const float* bias; float* Cout; __half* Couth;
    int aRow0, rowBase, Mv, nb;
    bool small;
    {
        int b = blockIdx.x;
        if (b < 96) {
            int p = b >> 5, mt = (b >> 4) & 1, nt = b & 15;
            nb = nt * 128; aRow0 = mt * 128; rowBase = mt * 128; Mv = N1; small = false;
            W    = (p == 0) ? Wq1 : ((p == 1) ? Wk1 : Wv1);
            bias = (p == 0) ? bq1 : ((p == 1) ? bk1 : bv1);
            Cout  = (p == 2) ? g_v1 : (float*)0;                    // fp32 only for v
            Couth = (p == 0) ? g_q1h : ((p == 1) ? g_k1h : (__half*)0);
        } else {
            int b2 = b - 96, p = b2 >> 4, nt = b2 & 15;
            nb = nt * 128; aRow0 = 256; rowBase = 0; Mv = N2; small = true;
            W    = (p == 0) ? Wq2 : ((p == 1) ? Wk2 : Wv2);
            bias = (p == 0) ? bq2 : ((p == 1) ? bk2 : bv2);
            Cout  = (p == 2) ? g_v2 : (float*)0;
            Couth = (p == 0) ? g_q2h : ((p == 1) ? g_k2h : (__half*)0);
        }
    }

    unsigned* Asm = proj_smem + sub * SUB_WORDS;     // 4 A stages
    unsigned* Bsm = Asm + 4 * ABUF_WORDS;            // 3 B stages
    uint32_t AsmU32, BsmU32;
    asm("{ .reg .u64 t; cvta.to.shared.u64 t, %1; cvt.u32.u64 %0, t; }" : "=r"(AsmU32) : "l"(Asm));
    asm("{ .reg .u64 t; cvta.to.shared.u64 t, %1; cvt.u32.u64 %0, t; }" : "=r"(BsmU32) : "l"(Bsm));

    // ---- producer addressing (within sub) ----
    const int rB = st >> 1, hB = st & 1;             // B: 2 thr/row, 16 fp32
    const int rA = st & 127, hA = (st >> 7) & 1;     // A: 2 thr/row, 16 fp16
    const float*  bp = W + (size_t)(nb + rB) * D + hB * 16;
    const __half* ap = g_xh + (size_t)(aRow0 + rA) * D + hA * 16;
    unsigned* bDst = Bsm + rB * ROWW + hB * 8;
    uint32_t aDstBase;
    {
        unsigned* p0 = Asm + rA * ROWW + hA * 8;
        asm("{ .reg .u64 t; cvta.to.shared.u64 t, %1; cvt.u32.u64 %0, t; }"
            : "=r"(aDstBase) : "l"(p0));
    }

    // ---- consumer addressing (ldmatrix lane offsets, byte units) ----
    const int warpM = (wid8 & 1) * 64;
    const int warpN = (wid8 >> 1) * 32;
    const int q = lane >> 2, c = lane & 3;
    const uint32_t aoff = (uint32_t)(((lane & 7) + ((lane >> 3) & 1) * 8) * 80 + (lane >> 4) * 16);
    const uint32_t boff = (uint32_t)(lane * 80);
    const uint32_t aBase0 = AsmU32 + (uint32_t)(warpM * 80) + aoff;
    const uint32_t bBase0 = BsmU32 + (uint32_t)(warpN * 80) + boff;

    // x2 tiles: warpM=64 warps have no live output rows; warpM=0 needs only i<2 (rows 0..31)
    const bool doCompute = !small || (warpM == 0);
    const int  iMax = small ? 2 : 4;

    float acc[4][4][4];
#pragma unroll
    for (int i = 0; i < 4; ++i)
#pragma unroll
        for (int j = 0; j < 4; ++j)
#pragma unroll
            for (int r = 0; r < 4; ++r) acc[i][j][r] = 0.f;

    float4 s0, s1, s2, s3;      // single B staging set

#define BAR_SUB() asm volatile("bar.sync %0, %1;" :: "r"(sub + 1), "r"(256) : "memory")

#define LDGB(g) do {                                                     \
        const float4* bp4 = (const float4*)(bp + (g) * 32);              \
        s0 = bp4[0]; s1 = bp4[1]; s2 = bp4[2]; s3 = bp4[3];              \
    } while (0)

#define STSB(buf) do {                                                   \
        __half2 p0 = __float22half2_rn(make_float2(s0.x, s0.y));         \
        __half2 p1 = __float22half2_rn(make_float2(s0.z, s0.w));         \
        __half2 p2 = __float22half2_rn(make_float2(s1.x, s1.y));         \
        __half2 p3 = __float22half2_rn(make_float2(s1.z, s1.w));         \
        __half2 p4 = __float22half2_rn(make_float2(s2.x, s2.y));         \
        __half2 p5 = __float22half2_rn(make_float2(s2.z, s2.w));         \
        __half2 p6 = __float22half2_rn(make_float2(s3.x, s3.y));         \
        __half2 p7 = __float22half2_rn(make_float2(s3.z, s3.w));         \
        uint4* bd = (uint4*)(bDst + (buf) * BBUF_WORDS);                 \
        bd[0] = make_uint4(*(unsigned*)&p0, *(unsigned*)&p1,             \
                           *(unsigned*)&p2, *(unsigned*)&p3);            \
        bd[1] = make_uint4(*(unsigned*)&p4, *(unsigned*)&p5,             \
                           *(unsigned*)&p6, *(unsigned*)&p7);            \
    } while (0)

#define CPA(ia) do {                                                     \
        uint32_t dst = aDstBase + (unsigned)(((ia) & 3) * ABUF_WORDS) * 4u; \
        const __half* src = ap + (size_t)(2 * (ia) + sub) * 32;          \
        asm volatile("cp.async.ca.shared.global [%0], [%1], 16;"         \
                     :: "r"(dst), "l"(src));                             \
        asm volatile("cp.async.ca.shared.global [%0], [%1], 16;"         \
                     :: "r"(dst + 16), "l"(src + 8));                    \
        asm volatile("cp.async.commit_group;" ::: "memory");             \
    } while (0)

#define COMPUTE(as, bs) do {                                             \
        if (doCompute) {                                                 \
            const uint32_t Aa = aBase0 + (uint32_t)((as) * ABUF_BYTES);  \
            const uint32_t Ba = bBase0 + (uint32_t)((bs) * BBUF_BYTES);  \
            _Pragma("unroll")                                            \
            for (int s = 0; s < 2; ++s) {                                \
                unsigned bf[4][2];                                       \
                LDSM4(bf[0][0], bf[1][0], bf[2][0], bf[3][0], Ba + s * 32); \
                LDSM4(bf[0][1], bf[1][1], bf[2][1], bf[3][1], Ba + s * 32 + 16); \
                _Pragma("unroll")                                        \
                for (int i = 0; i < 4; ++i) {                            \
                    if (i < iMax) {                                      \
                        unsigned af[4];                                  \
                        LDSM4(af[0], af[1], af[2], af[3], Aa + i * (16 * 80) + s * 32); \
                        _Pragma("unroll")                                \
                        for (int j = 0; j < 4; ++j)                      \
                            mma16816(acc[i][j], af, bf[j]);              \
                    }                                                    \
                }                                                        \
            }                                                            \
        }                                                                \
    } while (0)

    // ---- prologue ----
    CPA(0); CPA(1); CPA(2);
    LDGB(sub);            // B for sub-iter 0 (global chunk = sub)
    STSB(0);
    LDGB(2 + sub);        // B for sub-iter 1

    int bcur = 0;
#pragma unroll 1
    for (int i = 0; i < 32; ++i) {
        int bnext = bcur + 1; if (bnext == 3) bnext = 0;
        if (i + 1 < 32) STSB(bnext);                 // stage B(i+1)
        if (i + 2 < 32) LDGB(2 * (i + 2) + sub);     // fetch B(i+2)
        if (i < 30)      asm volatile("cp.async.wait_group 2;" ::: "memory");
        else if (i == 30) asm volatile("cp.async.wait_group 1;" ::: "memory");
        else             asm volatile("cp.async.wait_group 0;" ::: "memory");
        BAR_SUB();
        if (i + 3 < 32) CPA(i + 3);                  // safe: post-barrier
        COMPUTE(i & 3, bcur);
        bcur = bnext;
    }

    // ---- reduction (sub1 acc -> smem, sub0 adds) + epilogue ----
    __syncthreads();
    float* red = (float*)proj_smem;                  // 128 x 132 fp32 pitch
    if (sub == 1 && doCompute) {
#pragma unroll
        for (int i = 0; i < 4; ++i) {
            if (i >= iMax) break;
            const int r0 = warpM + i * 16 + q;
#pragma unroll
            for (int j = 0; j < 4; ++j) {
                const int col = warpN + j * 8 + 2 * c;
                *(float2*)(red + r0 * 132 + col)       = make_float2(acc[i][j][0], acc[i][j][1]);
                *(float2*)(red + (r0 + 8) * 132 + col) = make_float2(acc[i][j][2], acc[i][j][3]);
            }
        }
    }
    __syncthreads();
    if (sub == 0 && doCompute) {
#pragma unroll
        for (int i = 0; i < 4; ++i) {
            if (i >= iMax) break;
            const int r0 = rowBase + warpM + i * 16 + q;
            const int rl = warpM + i * 16 + q;
            const bool ok0 = r0 < Mv, ok1 = (r0 + 8) < Mv;
            const bool okh0 = !small || (rl < 32);   // fp16 pad rows beyond 32 stay zero
            const bool okh1 = okh0;
#pragma unroll
            for (int j = 0; j < 4; ++j) {
                const int col = nb + warpN + j * 8 + 2 * c;
                const int cl = warpN + j * 8 + 2 * c;
                const float2 bv = *(const float2*)(bias + col);
                float2 e0 = *(const float2*)(red + rl * 132 + cl);
                float2 e1 = *(const float2*)(red + (rl + 8) * 132 + cl);
                float2 o0 = make_float2(acc[i][j][0] + e0.x + bv.x,
                                        acc[i][j][1] + e0.y + bv.y);
                float2 o1 = make_float2(acc[i][j][2] + e1.x + bv.x,
                                        acc[i][j][3] + e1.y + bv.y);
                if (Cout) {
                    if (ok0) *(float2*)(Cout + (size_t)r0 * D + col) = o0;
                    if (ok1) *(float2*)(Cout + (size_t)(r0 + 8) * D + col) = o1;
                }
                if (Couth) {
                    // fp16 buffers are padded (256/32 rows); write all rows in range,
                    // out-of-range M rows hold garbage*0 contributions? No: they must be
                    // ZERO for smma correctness -> write bias-only rows as computed
                    // (acc=0 for pad rows since A pad rows are zero, so o = bias; that
                    // is WRONG for pad rows: smma would see bias, not 0).
                    // Therefore: only write rows < Mv; pad rows were never written and
                    // remain zero from initialization.
                    if (ok0 && okh0) {
                        __half2 h = __float22half2_rn(o0);
                        *(unsigned*)(Couth + (size_t)r0 * D + col) = *(unsigned*)&h;
                    }
                    if (ok1 && okh1) {
                        __half2 h = __float22half2_rn(o1);
                        *(unsigned*)(Couth + (size_t)(r0 + 8) * D + col) = *(unsigned*)&h;
                    }
                }
            }
        }
    }
#undef BAR_SUB
#undef LDGB
#undef STSB
#undef CPA
#undef COMPUTE
}

// ------------------------- score GEMMs on tensor pipe -------------------------
// 128 CTAs x 256 thr: gemm = b>>6 (0: S2 = q1h.k2hT, 1: S1T = k1h.q2hT),
// mt = (b>>5)&1 M-tile of 128, ks = b&31 K-split of 64 (2 BK32 iterations).
__global__ void __launch_bounds__(256) smma_kernel()
{
    __shared__ unsigned As[2][128 * ROWW];
    __shared__ unsigned Bs[2][32 * ROWW];
    const int tid = threadIdx.x, lane = tid & 31, w = tid >> 5;
    const int b = blockIdx.x;
    const int gemm = b >> 6, mt = (b >> 5) & 1, ks = b & 31;
    const __half* Ah = gemm ? g_k1h : g_q1h;
    const __half* Bh = gemm ? g_q2h : g_k2h;
    float* S = gS[gemm];

    const int rA = tid & 127, hA = tid >> 7;
    const __half* apA = Ah + (size_t)(mt * 128 + rA) * D + ks * 64 + hA * 16;
    const int rB = tid >> 2, qb = tid & 3;           // tid<128 only
    const __half* apB = Bh + (size_t)rB * D + ks * 64 + qb * 8;

    uint32_t aDst, bDst, AsU, BsU;
    { unsigned* p = &As[0][rA * ROWW + hA * 8];
      asm("{ .reg .u64 t; cvta.to.shared.u64 t, %1; cvt.u32.u64 %0, t; }" : "=r"(aDst) : "l"(p)); }
    { unsigned* p = &Bs[0][rB * ROWW + qb * 4];
      asm("{ .reg .u64 t; cvta.to.shared.u64 t, %1; cvt.u32.u64 %0, t; }" : "=r"(bDst) : "l"(p)); }
    asm("{ .reg .u64 t; cvta.to.shared.u64 t, %1; cvt.u32.u64 %0, t; }" : "=r"(AsU) : "l"(&As[0][0]));
    asm("{ .reg .u64 t; cvta.to.shared.u64 t, %1; cvt.u32.u64 %0, t; }" : "=r"(BsU) : "l"(&Bs[0][0]));

    const uint32_t aoff = (uint32_t)(((lane & 7) + ((lane >> 3) & 1) * 8) * 80 + (lane >> 4) * 16);
    const uint32_t aBase = AsU + (uint32_t)(w * 16 * 80) + aoff;
    const uint32_t bBase = BsU + (uint32_t)(lane * 80);

    float acc[4][4];
#pragma unroll
    for (int j = 0; j < 4; ++j)
#pragma unroll
        for (int r = 0; r < 4; ++r) acc[j][r] = 0.f;

#define SCPA(cc, buf) do {                                               \
        uint32_t da = aDst + (buf) * (128 * ROWW * 4);                   \
        const __half* sa = apA + (cc) * 32;                              \
        asm volatile("cp.async.ca.shared.global [%0], [%1], 16;" :: "r"(da), "l"(sa)); \
        asm volatile("cp.async.ca.shared.global [%0], [%1], 16;" :: "r"(da + 16), "l"(sa + 8)); \
        if (tid < 128) {                                                 \
            uint32_t db = bDst + (buf) * (32 * ROWW * 4);                \
            const __half* sb = apB + (cc) * 32;                          \
            asm volatile("cp.async.ca.shared.global [%0], [%1], 16;" :: "r"(db), "l"(sb)); \
        }                                                                \
        asm volatile("cp.async.commit_group;" ::: "memory");             \
    } while (0)

    SCPA(0, 0); SCPA(1, 1);
#pragma unroll
    for (int cc = 0; cc < 2; ++cc) {
        if (cc == 0) asm volatile("cp.async.wait_group 1;" ::: "memory");
        else         asm volatile("cp.async.wait_group 0;" ::: "memory");
        __syncthreads();
        const int buf = cc & 1;
        const uint32_t Aa = aBase + (uint32_t)(buf * (128 * ROWW * 4));
        const uint32_t Ba = bBase + (uint32_t)(buf * (32 * ROWW * 4));
#pragma unroll
        for (int s = 0; s < 2; ++s) {
            unsigned bf0[4], bf1[4], af[4];
            LDSM4(bf0[0], bf0[1], bf0[2], bf0[3], Ba + s * 32);
            LDSM4(bf1[0], bf1[1], bf1[2], bf1[3], Ba + s * 32 + 16);
            LDSM4(af[0], af[1], af[2], af[3], Aa + s * 32);
#pragma unroll
            for (int j = 0; j < 4; ++j) {
                unsigned bb[2] = { bf0[j], bf1[j] };
                mma16816(acc[j], af, bb);
            }
        }
        __syncthreads();
    }
#undef SCPA

    const int q = lane >> 2, c2 = lane & 3;
    const int m0 = mt * 128 + w * 16 + q;
#pragma unroll
    for (int j = 0; j < 4; ++j) {
        const int n = j * 8 + 2 * c2;
        atomicAdd(&S[m0 * 32 + n],           acc[j][0]);
        atomicAdd(&S[m0 * 32 + n + 1],       acc[j][1]);
        atomicAdd(&S[(m0 + 8) * 32 + n],     acc[j][2]);
        atomicAdd(&S[(m0 + 8) * 32 + n + 1], acc[j][3]);
    }
}

// ------------------------- finish: sigmoid + probs + fc + ctx -------------------------
// 554 blocks: b<500 -> ctx2/probs2 (m = b>>1, half = b&1); else ctx1/probs1.
__global__ void __launch_bounds__(256) finish_kernel(
    const float* __restrict__ w_fc1, const float* __restrict__ b_fc1,
    const float* __restrict__ w_fc2, const float* __restrict__ b_fc2,
    float* __restrict__ out)
{
    __shared__ float ps[32];
    __shared__ float red[8];
    const int tid = threadIdx.x;
    const int lane = tid & 31, w = tid >> 5;

    float* out_ctx2   = out;                                  // 16B-aligned
    float* out_probs2 = out + (size_t)N1 * D;
    float* out_ctx1   = out + (size_t)N1 * D + N1 * N2;       // 8B-aligned ONLY
    float* out_probs1 = out + (size_t)N1 * D + N1 * N2 + (size_t)N2 * D;

    if (blockIdx.x < 2 * N1) {
        const int m = blockIdx.x >> 1;
        const int half = blockIdx.x & 1;
        const int o4 = half * 256 + tid;             // float4 index into row
        float4 v = *(const float4*)(g_v1 + (size_t)m * D + o4 * 4);   // hoisted load
        if (tid < N2) {
            float s = gS[0][m * 32 + tid];
            float pr = 1.f / (1.f + expf(-s * SCALE));
            ps[tid] = pr;
            if (half == 0) out_probs2[(size_t)m * N2 + tid] = pr;
        }
        __syncthreads();
        float r2 = 0.f;
#pragma unroll
        for (int n = 0; n < N2; ++n) r2 += ps[n] * w_fc2[n];
        const float bf2 = b_fc2[0];
        float4 o = make_float4(v.x * r2 + bf2, v.y * r2 + bf2,
                               v.z * r2 + bf2, v.w * r2 + bf2);
        *(float4*)(out_ctx2 + (size_t)m * D + o4 * 4) = o;
    } else {
        const int j = blockIdx.x - 2 * N1;
        const int t = j >> 1;
        const int half = j & 1;
        const int o4 = half * 256 + tid;
        float4 v = *(const float4*)(g_v2 + (size_t)t * D + o4 * 4);   // hoisted load
        float acc = 0.f;
        if (tid < N1) {
            float s = gS[1][tid * 32 + t];
            float pr = 1.f / (1.f + expf(-s * SCALE));
            if (half == 0) out_probs1[(size_t)t * N1 + tid] = pr;
            acc = pr * w_fc1[tid];
        }
#pragma unroll
        for (int o = 16; o; o >>= 1) acc += __shfl_xor_sync(0xffffffffu, acc, o);
        if (lane == 0) red[w] = acc;
        __syncthreads();
        float r1 = 0.f;
#pragma unroll
        for (int ww = 0; ww < 8; ++ww) r1 += red[ww];
        const float bf1 = b_fc1[0];
        // out_ctx1 only 8B-aligned: two float2 stores.
        float* dst = out_ctx1 + (size_t)t * D + o4 * 4;
        *(float2*)(dst)     = make_float2(v.x * r1 + bf1, v.y * r1 + bf1);
        *(float2*)(dst + 2) = make_float2(v.z * r1 + bf1, v.w * r1 + bf1);
    }
}

// ------------------------- launch -------------------------
extern "C" void kernel_launch(void* const* d_in, const int* in_sizes, int n_in,
                              void* d_out, int out_size)
{
    const float* x1  = (const float*)d_in[0];
    const float* x2  = (const float*)d_in[1];
    const float* Wq1 = (const float*)d_in[2];
    const float* bq1 = (const float*)d_in[3];
    const float* Wk1 = (const float*)d_in[4];
    const float* bk1 = (const float*)d_in[5];
    const float* Wv1 = (const float*)d_in[6];
    const float* bv1 = (const float*)d_in[7];
    const float* Wq2 = (const float*)d_in[8];
    const float* bq2 = (const float*)d_in[9];
    const float* Wk2 = (const float*)d_in[10];
    const float* bk2 = (const float*)d_in[11];
    const float* Wv2 = (const float*)d_in[12];
    const float* bv2 = (const float*)d_in[13];
    const float* wf1 = (const float*)d_in[14];
    const float* bf1 = (const float*)d_in[15];
    const float* wf2 = (const float*)d_in[16];
    const float* bf2 = (const float*)d_in[17];
    float* out = (float*)d_out;

    static int smem_set = 0;
    if (!smem_set) {
        cudaFuncSetAttribute(proj_kernel, cudaFuncAttributeMaxDynamicSharedMemorySize, PROJ_SMEM);
        smem_set = 1;
    }

    prep_kernel<<<448, 256>>>(x1, x2);
    proj_kernel<<<144, 512, PROJ_SMEM>>>(Wq1, Wk1, Wv1, Wq2, Wk2, Wv2,
                                         bq1, bk1, bv1, bq2, bk2, bv2);
    smma_kernel<<<128, 256>>>();
    finish_kernel<<<2 * N1 + 2 * N2, 256>>>(wf1, bf1, wf2, bf2, out);
}